// round 13
// baseline (speedup 1.0000x reference)
#include <cuda_runtime.h>
#include <cuda_bf16.h>
#include <math.h>
#include <stdint.h>

#define D_IN   1024
#define D_H    2048
#define BATCH  256
#define D_OUT  1000
#define EPSV   1e-12f
#define STEPS  30

// ---- bf16 aux GEMM smem geometry (x_proj / head, 128-thread kernel) ----
#define ROW_B      144
#define TILE_A_HI  0
#define TILE_A_LO  9216
#define TILE_B_HI  18432
#define TILE_B_LO  27648
#define STAGE_BYTES 36864
#define SMEM_BYTES  (2 * STAGE_BYTES)

// ---- step GEMM smem: BK=64 panels, 4 tiles of 64 rows x 144B, 5 stages ----
#define SROW     144
#define STILE    9216                 // 64 * 144
#define S_AH     0
#define S_AL     9216
#define S_BH     18432
#define S_BL     27648
#define S_STAGE  36864
#define S_DATA   128                  // mbarriers below
#define NSTG     5
#define S_SMEM   (S_DATA + NSTG * S_STAGE)   // 184448
#define S_TX     36864                // bytes per stage

// panel block byte offset for element (row r, k) of a [.., 2048] matrix (BK=64)
#define NKCH     32                   // k chunks per 2048
__host__ __device__ __forceinline__ size_t pkoff(int r, int k) {
    return ((size_t)((r >> 6) * NKCH + (k >> 6))) * STILE +
           (size_t)(r & 63) * SROW + (size_t)((k & 63) << 1);
}

// ---------------- device scratch (no allocations allowed) ----------------
__device__ float g_t[D_IN];
__device__ float g_s[D_H];
__device__ float g_scal[4];              // [1] = 1/sigma
__device__ int   g_ticket;
__device__ float g_xpb[3][BATCH * D_H];  // xproj + bias_l
__device__ float g_hA[BATCH * D_H];
__device__ float g_hB[BATCH * D_H];

// packed (panel-layout) step operands
#define WPK_BYTES ((size_t)32 * NKCH * STILE)   // 9,437,184
#define HPK_BYTES ((size_t)4  * NKCH * STILE)   // 1,179,648
__device__ char g_W0hp[WPK_BYTES], g_W0lp[WPK_BYTES];
__device__ char g_W1hp[WPK_BYTES], g_W1lp[WPK_BYTES];
__device__ char g_W2hp[WPK_BYTES], g_W2lp[WPK_BYTES];
__device__ char g_hPhA[HPK_BYTES], g_hPlA[HPK_BYTES];
__device__ char g_hPhB[HPK_BYTES], g_hPlB[HPK_BYTES];

// plain bf16 splits (x_proj / head B operands)
__device__ __nv_bfloat16 g_Winhi[D_H * D_IN], g_Winlo[D_H * D_IN];
__device__ __nv_bfloat16 g_Hdhi[D_OUT * D_H], g_Hdlo[D_OUT * D_H];
__device__ __nv_bfloat16 g_xhi[BATCH * D_IN], g_xlo[BATCH * D_IN];

// ---------------- portable PTX helpers ----------------
__device__ __forceinline__ uint32_t smem_u32(const void* p) {
    uint32_t a;
    asm("{ .reg .u64 t; cvta.to.shared.u64 t, %1; cvt.u32.u64 %0, t; }" : "=r"(a) : "l"(p));
    return a;
}
#define CP16(dst, src) asm volatile("cp.async.cg.shared.global [%0], [%1], 16;" :: "r"(dst), "l"(src))
#define CP_COMMIT()    asm volatile("cp.async.commit_group;" ::: "memory")
#define CP_WAIT(n)     asm volatile("cp.async.wait_group %0;" :: "n"(n) : "memory")

#define MBAR_INIT(a, c) asm volatile("mbarrier.init.shared.b64 [%0], %1;" :: "r"(a), "r"(c) : "memory")
#define MBAR_EXPECT(a, bytes) \
    asm volatile("mbarrier.arrive.expect_tx.shared.b64 _, [%0], %1;" :: "r"(a), "r"(bytes) : "memory")
#define BULKT(dst, src, mbar) \
    asm volatile("cp.async.bulk.shared::cluster.global.mbarrier::complete_tx::bytes [%0], [%1], 9216, [%2];" \
        :: "r"(dst), "l"(src), "r"(mbar) : "memory")
#define MBAR_WAIT(mbar, parity) do {                                              \
    uint32_t _m = (mbar), _p = (parity), _d;                                      \
    asm volatile("{ .reg .pred p; mbarrier.try_wait.parity.acquire.cta.shared::cta.b64 p, [%1], %2; selp.b32 %0, 1, 0, p; }" \
        : "=r"(_d) : "r"(_m), "r"(_p) : "memory");                                \
    if (!_d) {                                                                    \
        asm volatile("{ .reg .pred P1; WL_%=: mbarrier.try_wait.parity.acquire.cta.shared::cta.b64 P1, [%0], %1, 0x989680; @P1 bra.uni WD_%=; bra.uni WL_%=; WD_%=: }" \
            :: "r"(_m), "r"(_p) : "memory");                                      \
    }                                                                             \
} while (0)

__device__ __forceinline__ void ldsm4(uint32_t* r, uint32_t addr) {
    asm volatile("ldmatrix.sync.aligned.m8n8.x4.shared.b16 {%0,%1,%2,%3}, [%4];"
        : "=r"(r[0]), "=r"(r[1]), "=r"(r[2]), "=r"(r[3]) : "r"(addr));
}
__device__ __forceinline__ void mma_bf16(float* c, const uint32_t* a, const uint32_t* b) {
    asm volatile("mma.sync.aligned.m16n8k16.row.col.f32.bf16.bf16.f32 "
        "{%0,%1,%2,%3}, {%4,%5,%6,%7}, {%8,%9}, {%0,%1,%2,%3};"
        : "+f"(c[0]), "+f"(c[1]), "+f"(c[2]), "+f"(c[3])
        : "r"(a[0]), "r"(a[1]), "r"(a[2]), "r"(a[3]), "r"(b[0]), "r"(b[1]));
}

// ---------------- prep: splits + packing + h0 zeros + matvec_t + ticket reset ----
__device__ __forceinline__ void split_plain(const float* __restrict__ src,
        __nv_bfloat16* __restrict__ hi, __nv_bfloat16* __restrict__ lo, int i) {
    float a = src[i];
    __nv_bfloat16 h = __float2bfloat16(a);
    hi[i] = h;
    lo[i] = __float2bfloat16(a - __bfloat162float(h));
}
__device__ __forceinline__ void split_pack(const float* __restrict__ src,
        char* __restrict__ hp, char* __restrict__ lp, int i) {
    const int r = i >> 11, k = i & 2047;
    const size_t off = pkoff(r, k);
    float a = src[i];
    __nv_bfloat16 h = __float2bfloat16(a);
    *reinterpret_cast<__nv_bfloat16*>(hp + off) = h;
    *reinterpret_cast<__nv_bfloat16*>(lp + off) =
        __float2bfloat16(a - __bfloat162float(h));
}

__global__ void prep_kernel(const float* __restrict__ W0, const float* __restrict__ W1,
                            const float* __restrict__ W2, const float* __restrict__ Win,
                            const float* __restrict__ Hd, const float* __restrict__ x,
                            const float* __restrict__ u) {
    const int stride = gridDim.x * blockDim.x;
    const int t0 = blockIdx.x * blockDim.x + threadIdx.x;
    if (t0 == 0) g_ticket = 0;
    for (int i = t0; i < D_H * D_H; i += stride) {
        split_pack(W0, g_W0hp, g_W0lp, i);
        split_pack(W1, g_W1hp, g_W1lp, i);
        split_pack(W2, g_W2hp, g_W2lp, i);
    }
    for (int i = t0; i < D_H * D_IN; i += stride) split_plain(Win, g_Winhi, g_Winlo, i);
    for (int i = t0; i < D_OUT * D_H; i += stride) split_plain(Hd, g_Hdhi, g_Hdlo, i);
    for (int i = t0; i < BATCH * D_IN; i += stride) split_plain(x, g_xhi, g_xlo, i);
    for (int i = t0; i < BATCH * D_H; i += stride) g_hA[i] = 0.0f;
    for (int i = t0; i < (int)(HPK_BYTES / 4); i += stride) {
        reinterpret_cast<uint32_t*>(g_hPhA)[i] = 0u;
        reinterpret_cast<uint32_t*>(g_hPlA)[i] = 0u;
    }
    for (int j = t0; j < D_IN; j += stride) {
        float acc = 0.0f;
#pragma unroll 4
        for (int i = 0; i < D_H; i++) acc = fmaf(Win[(size_t)i * D_IN + j], u[i], acc);
        g_t[j] = acc;
    }
}

// ---------------- sigma: matvec_s + final reduce, ticket-synced ----------------
__global__ void sigma_kernel(const float* __restrict__ W, const float* __restrict__ t,
                             float* __restrict__ s, float* __restrict__ scal) {
    __shared__ float shw[8];
    __shared__ int lastf;
    const int tid = threadIdx.x;
    const int lane = tid & 31;
    const int w = tid >> 5;
    float ss = 0.0f;
#pragma unroll
    for (int i = 0; i < 4; i++) {
        float v = t[tid + (i << 8)];
        ss = fmaf(v, v, ss);
    }
#pragma unroll
    for (int o = 16; o > 0; o >>= 1) ss += __shfl_xor_sync(0xffffffffu, ss, o);
    if (lane == 0) shw[w] = ss;
    __syncthreads();
    float tot = shw[lane & 7];
#pragma unroll
    for (int o = 4; o > 0; o >>= 1) tot += __shfl_xor_sync(0xffffffffu, tot, o);
    const float invn = 1.0f / (sqrtf(tot) + EPSV);

    const int gwarp = blockIdx.x * 8 + w;
    for (int r = gwarp; r < D_H; r += 512) {
        const float* row = W + (size_t)r * D_IN;
        float acc = 0.0f;
        for (int j = lane; j < D_IN; j += 32) acc = fmaf(row[j], t[j], acc);
#pragma unroll
        for (int o = 16; o > 0; o >>= 1) acc += __shfl_xor_sync(0xffffffffu, acc, o);
        if (lane == 0) s[r] = acc * invn;
    }
    __threadfence();
    if (tid == 0) lastf = (atomicAdd(&g_ticket, 1) == (int)gridDim.x - 1);
    __syncthreads();
    if (lastf) {
        __threadfence();
        float q = 0.0f;
        for (int i = tid; i < D_H; i += 256) { float v = s[i]; q = fmaf(v, v, q); }
#pragma unroll
        for (int o = 16; o > 0; o >>= 1) q += __shfl_xor_sync(0xffffffffu, q, o);
        if (lane == 0) shw[w] = q;
        __syncthreads();
        if (tid == 0) {
            float Q = 0.0f;
#pragma unroll
            for (int i = 0; i < 8; i++) Q += shw[i];
            scal[1] = (sqrtf(Q) + EPSV) / Q;
        }
    }
}

// ================= bf16 3-pass aux GEMM =================
template <int AP>
__device__ __forceinline__ void prefetch_chunk(uint32_t sb_u, char* sb_p, int k0,
        const void* Ahi, const void* Alo,
        const __nv_bfloat16* __restrict__ Bhi, const __nv_bfloat16* __restrict__ Blo,
        int K, int NB, int m0, int n0) {
    const int t = threadIdx.x;
#pragma unroll
    for (int r = 0; r < 4; r++) {
        const int idx = t + (r << 7);
        const int row = idx >> 3;
        const int c   = idx & 7;
        const uint32_t soff = (uint32_t)row * ROW_B + (c << 4);
        const void *pa, *pl;
        if (AP == 0) {
            const size_t ga = (size_t)(m0 + row) * K + k0 + (c << 3);
            pa = (const __nv_bfloat16*)Ahi + ga;
            pl = (const __nv_bfloat16*)Alo + ga;
        } else {
            const size_t gb = ((size_t)((m0 >> 6) * NKCH + (k0 >> 6))) * STILE +
                              (size_t)row * SROW + (c << 4);
            pa = (const char*)Ahi + gb;
            pl = (const char*)Alo + gb;
        }
        CP16(sb_u + TILE_A_HI + soff, pa);
        CP16(sb_u + TILE_A_LO + soff, pl);
        const int gn = n0 + row;
        if (gn < NB) {
            const size_t gb2 = (size_t)gn * K + k0 + (c << 3);
            CP16(sb_u + TILE_B_HI + soff, Bhi + gb2);
            CP16(sb_u + TILE_B_LO + soff, Blo + gb2);
        } else {
            const uint4 z = make_uint4(0, 0, 0, 0);
            *reinterpret_cast<uint4*>(sb_p + TILE_B_HI + soff) = z;
            *reinterpret_cast<uint4*>(sb_p + TILE_B_LO + soff) = z;
        }
    }
}

template <int MODE, int AP>
__global__ void __launch_bounds__(128)
gemm_mma(const void* Ahi, const void* Alo,
         const __nv_bfloat16* __restrict__ Bhi, const __nv_bfloat16* __restrict__ Blo,
         const float* __restrict__ bias, float* __restrict__ outF,
         const float* __restrict__ scale_ptr, int K, int NB, int ldOut,
         const float* __restrict__ lb0, const float* __restrict__ lb1,
         const float* __restrict__ lb2, float* __restrict__ xpb) {
    extern __shared__ char smem[];
    const uint32_t sbase = smem_u32(smem);
    const int tid  = threadIdx.x;
    const int lane = tid & 31;
    const int wid  = tid >> 5;
    const int m0 = blockIdx.y * 64;
    const int n0 = blockIdx.x * 64;
    const int wm = (wid >> 1) << 5;
    const int wn = (wid & 1) << 5;
    const int NC = K >> 6;

    const int arow  = (lane & 7) | (((lane >> 3) & 1) << 3);
    const int akoff = ((lane >> 4) & 1) << 3;
    const int brow  = (lane & 7) | (((lane >> 4) & 1) << 3);
    const int bkoff = ((lane >> 3) & 1) << 3;

    float acc[2][4][4] = {};

    prefetch_chunk<AP>(sbase, smem, 0, Ahi, Alo, Bhi, Blo, K, NB, m0, n0);
    CP_COMMIT();

    for (int c = 0; c < NC; c++) {
        if (c + 1 < NC) {
            const int ns = (c + 1) & 1;
            prefetch_chunk<AP>(sbase + ns * STAGE_BYTES, smem + ns * STAGE_BYTES,
                               (c + 1) << 6, Ahi, Alo, Bhi, Blo, K, NB, m0, n0);
            CP_COMMIT();
            CP_WAIT(1);
        } else {
            CP_WAIT(0);
        }
        __syncthreads();

        const uint32_t st = sbase + (c & 1) * STAGE_BYTES;
#pragma unroll
        for (int kk = 0; kk < 4; kk++) {
            const int k0 = kk << 4;
            uint32_t ah[2][4], al[2][4], bh[2][4], bl[2][4];
#pragma unroll
            for (int a = 0; a < 2; a++) {
                const uint32_t off = (uint32_t)(wm + (a << 4) + arow) * ROW_B +
                                     ((k0 + akoff) << 1);
                ldsm4(ah[a], st + TILE_A_HI + off);
                ldsm4(al[a], st + TILE_A_LO + off);
            }
#pragma unroll
            for (int b = 0; b < 2; b++) {
                const uint32_t off = (uint32_t)(wn + (b << 4) + brow) * ROW_B +
                                     ((k0 + bkoff) << 1);
                ldsm4(bh[b], st + TILE_B_HI + off);
                ldsm4(bl[b], st + TILE_B_LO + off);
            }
#pragma unroll
            for (int a = 0; a < 2; a++)
#pragma unroll
                for (int j = 0; j < 4; j++)
                    mma_bf16(acc[a][j], ah[a], &bh[j >> 1][(j & 1) << 1]);
#pragma unroll
            for (int a = 0; a < 2; a++)
#pragma unroll
                for (int j = 0; j < 4; j++)
                    mma_bf16(acc[a][j], ah[a], &bl[j >> 1][(j & 1) << 1]);
#pragma unroll
            for (int a = 0; a < 2; a++)
#pragma unroll
                for (int j = 0; j < 4; j++)
                    mma_bf16(acc[a][j], al[a], &bh[j >> 1][(j & 1) << 1]);
        }
        __syncthreads();
    }

    const float scale = (MODE == 0) ? *scale_ptr : 1.0f;
    const int g  = lane >> 2;
    const int i2 = (lane & 3) << 1;
#pragma unroll
    for (int a = 0; a < 2; a++)
#pragma unroll
        for (int j = 0; j < 4; j++)
#pragma unroll
            for (int e = 0; e < 4; e++) {
                const int m = m0 + wm + (a << 4) + g + ((e >> 1) << 3);
                const int n = n0 + wn + (j << 3) + i2 + (e & 1);
                const float r = acc[a][j][e];
                if (MODE == 0) {
                    const float v = fmaf(r, scale, bias[n]);
                    const size_t idx = (size_t)m * D_H + n;
                    xpb[idx] = v + lb0[n];
                    xpb[(size_t)BATCH * D_H + idx] = v + lb1[n];
                    xpb[(size_t)2 * BATCH * D_H + idx] = v + lb2[n];
                } else {
                    if (n < NB) outF[(size_t)m * ldOut + n] = r + bias[n];
                }
            }
}

// ========== step GEMM: 8 warps split-K, BK=64, 5-stage deep bulk pipeline ========
// grid = (mt=4, nt=32): consecutive CTAs share the B (weight) panel -> L2 dedup.
__device__ __forceinline__ void issue_chunk(uint32_t st_u, uint32_t mbar, int chunk,
        const char* __restrict__ AH, const char* __restrict__ AL,
        const char* __restrict__ BH, const char* __restrict__ BL, int mt, int nt) {
    const size_t ab = ((size_t)(mt * NKCH + chunk)) * STILE;
    const size_t bb = ((size_t)(nt * NKCH + chunk)) * STILE;
    BULKT(st_u + S_AH, AH + ab, mbar);
    BULKT(st_u + S_AL, AL + ab, mbar);
    BULKT(st_u + S_BH, BH + bb, mbar);
    BULKT(st_u + S_BL, BL + bb, mbar);
}

__global__ void __launch_bounds__(256)
gemm_step(const char* __restrict__ AH, const char* __restrict__ AL,
          const char* __restrict__ BH, const char* __restrict__ BL,
          const float* __restrict__ xpb, const float* __restrict__ hold,
          float* __restrict__ outF,
          char* __restrict__ outHp, char* __restrict__ outLp) {
    extern __shared__ char smem[];
    const uint32_t sbase = smem_u32(smem);
    const uint32_t data0 = sbase + S_DATA;
    const int tid  = threadIdx.x;
    const int lane = tid & 31;
    const int wid  = tid >> 5;
    const int wk   = wid & 1;         // k half
    const int wq   = wid >> 1;        // 0..3 output warp-tile
    const int mt = blockIdx.x;        // 0..3   (A row tile)
    const int nt = blockIdx.y;        // 0..31  (B row tile) — consecutive x share B
    const int m0 = mt << 6;
    const int n0 = nt << 6;
    const int wm = (wq >> 1) << 5;
    const int wn = (wq & 1) << 5;
    const int NC = NKCH;              // 32 chunks of 64

    const int arow  = (lane & 7) | (((lane >> 3) & 1) << 3);
    const int akoff = ((lane >> 4) & 1) << 3;
    const int brow  = (lane & 7) | (((lane >> 4) & 1) << 3);
    const int bkoff = ((lane >> 3) & 1) << 3;
    const int kbase = wk << 1;        // kki 0-1 or 2-3

    float accm[2][4][4] = {};
    float acc1[2][4][4] = {};
    float acc2[2][4][4] = {};

    if (tid == 0) {
#pragma unroll
        for (int i = 0; i < NSTG; i++) MBAR_INIT(sbase + (i << 4), 1);
    }
    __syncthreads();
    if (tid == 0) {
#pragma unroll
        for (int i = 0; i < 4; i++) {       // prologue: 4 chunks in flight
            MBAR_EXPECT(sbase + (i << 4), S_TX);
            issue_chunk(data0 + i * S_STAGE, sbase + (i << 4), i, AH, AL, BH, BL, mt, nt);
        }
    }

    for (int c = 0; c < NC; c++) {
        const int q = c / NSTG;
        const int s = c - q * NSTG;
        if (c + 4 < NC) {
            __syncthreads();   // all warps done reading the stage being reused
            if (tid == 0) {
                const int c2 = c + 4;
                const int q2 = c2 / NSTG;
                const int s2 = c2 - q2 * NSTG;
                MBAR_EXPECT(sbase + (s2 << 4), S_TX);
                issue_chunk(data0 + s2 * S_STAGE, sbase + (s2 << 4), c2,
                            AH, AL, BH, BL, mt, nt);
            }
        }
        MBAR_WAIT(sbase + (s << 4), q & 1);

        const uint32_t st = data0 + s * S_STAGE;
#pragma unroll
        for (int kki = 0; kki < 2; kki++) {
            const int k0 = (kbase + kki) << 4;
            uint32_t ah[2][4], al[2][4], bh[2][4], bl[2][4];
#pragma unroll
            for (int a = 0; a < 2; a++) {
                const uint32_t off = (uint32_t)(wm + (a << 4) + arow) * SROW +
                                     ((k0 + akoff) << 1);
                ldsm4(ah[a], st + S_AH + off);
                ldsm4(al[a], st + S_AL + off);
            }
#pragma unroll
            for (int b = 0; b < 2; b++) {
                const uint32_t off = (uint32_t)(wn + (b << 4) + brow) * SROW +
                                     ((k0 + bkoff) << 1);
                ldsm4(bh[b], st + S_BH + off);
                ldsm4(bl[b], st + S_BL + off);
            }
#pragma unroll
            for (int a = 0; a < 2; a++)
#pragma unroll
                for (int j = 0; j < 4; j++) {
                    mma_bf16(accm[a][j], ah[a], &bh[j >> 1][(j & 1) << 1]);
                    mma_bf16(acc1[a][j], ah[a], &bl[j >> 1][(j & 1) << 1]);
                    mma_bf16(acc2[a][j], al[a], &bh[j >> 1][(j & 1) << 1]);
                }
        }
    }

    // reduce the 3 banks locally
    float rsum[2][4][4];
#pragma unroll
    for (int a = 0; a < 2; a++)
#pragma unroll
        for (int j = 0; j < 4; j++)
#pragma unroll
            for (int e = 0; e < 4; e++)
                rsum[a][j][e] = accm[a][j][e] + acc1[a][j][e] + acc2[a][j][e];

    // cross-warp k reduction via (now dead) stage smem: layout [wq][elem][lane]
    __syncthreads();
    float* red = reinterpret_cast<float*>(smem + S_DATA);
    if (wk == 1) {
        float* dst = red + (wq << 10);
#pragma unroll
        for (int a = 0; a < 2; a++)
#pragma unroll
            for (int j = 0; j < 4; j++)
#pragma unroll
                for (int e = 0; e < 4; e++)
                    dst[((a << 4) | (j << 2) | e) << 5 | lane] = rsum[a][j][e];
    }
    __syncthreads();
    if (wk == 0) {
        const float* src = red + (wq << 10);
#pragma unroll
        for (int a = 0; a < 2; a++)
#pragma unroll
            for (int j = 0; j < 4; j++)
#pragma unroll
                for (int e = 0; e < 4; e++)
                    rsum[a][j][e] += src[((a << 4) | (j << 2) | e) << 5 | lane];

        // epilogue: fp32 h (plain) + bf16 hi/lo limbs (packed panel layout)
        const int g  = lane >> 2;
        const int i2 = (lane & 3) << 1;
#pragma unroll
        for (int a = 0; a < 2; a++)
#pragma unroll
            for (int j = 0; j < 4; j++)
#pragma unroll
                for (int eh = 0; eh < 2; eh++) {
                    const int m = m0 + wm + (a << 4) + g + (eh << 3);
                    const int n = n0 + wn + (j << 3) + i2;
                    const size_t idx = (size_t)m * D_H + n;
                    const float r0 = rsum[a][j][eh * 2 + 0];
                    const float r1 = rsum[a][j][eh * 2 + 1];
                    const float2 xb = *reinterpret_cast<const float2*>(xpb + idx);
                    const float2 ho = *reinterpret_cast<const float2*>(hold + idx);
                    const float hn0 = 0.5f * ho.x + 0.5f * tanhf(xb.x + r0);
                    const float hn1 = 0.5f * ho.y + 0.5f * tanhf(xb.y + r1);
                    *reinterpret_cast<float2*>(outF + idx) = make_float2(hn0, hn1);
                    const __nv_bfloat16 b0 = __float2bfloat16(hn0);
                    const __nv_bfloat16 b1 = __float2bfloat16(hn1);
                    __nv_bfloat162 hiv, lov;
                    hiv.x = b0; hiv.y = b1;
                    lov.x = __float2bfloat16(hn0 - __bfloat162float(b0));
                    lov.y = __float2bfloat16(hn1 - __bfloat162float(b1));
                    const size_t pidx = pkoff(m, n);
                    *reinterpret_cast<__nv_bfloat162*>(outHp + pidx) = hiv;
                    *reinterpret_cast<__nv_bfloat162*>(outLp + pidx) = lov;
                }
    }
}

// ---------------- host ----------------
extern "C" void kernel_launch(void* const* d_in, const int* in_sizes, int n_in,
                              void* d_out, int out_size) {
    const float* x     = (const float*)d_in[0];
    const float* Winw  = (const float*)d_in[1];
    const float* Winb  = (const float*)d_in[2];
    const float* u     = (const float*)d_in[3];
    const float* W0    = (const float*)d_in[4];
    const float* b0    = (const float*)d_in[5];
    const float* W1    = (const float*)d_in[6];
    const float* b1    = (const float*)d_in[7];
    const float* W2    = (const float*)d_in[8];
    const float* b2    = (const float*)d_in[9];
    const float* headw = (const float*)d_in[10];
    const float* headb = (const float*)d_in[11];
    float* out = (float*)d_out;

    float *t, *s, *scal, *hA, *hB, *xpb;
    cudaGetSymbolAddress((void**)&t, g_t);
    cudaGetSymbolAddress((void**)&s, g_s);
    cudaGetSymbolAddress((void**)&scal, g_scal);
    cudaGetSymbolAddress((void**)&xpb, g_xpb);
    cudaGetSymbolAddress((void**)&hA, g_hA);
    cudaGetSymbolAddress((void**)&hB, g_hB);
    char *W0hp, *W0lp, *W1hp, *W1lp, *W2hp, *W2lp, *hPhA, *hPlA, *hPhB, *hPlB;
    cudaGetSymbolAddress((void**)&W0hp, g_W0hp); cudaGetSymbolAddress((void**)&W0lp, g_W0lp);
    cudaGetSymbolAddress((void**)&W1hp, g_W1hp); cudaGetSymbolAddress((void**)&W1lp, g_W1lp);
    cudaGetSymbolAddress((void**)&W2hp, g_W2hp); cudaGetSymbolAddress((void**)&W2lp, g_W2lp);
    cudaGetSymbolAddress((void**)&hPhA, g_hPhA); cudaGetSymbolAddress((void**)&hPlA, g_hPlA);
    cudaGetSymbolAddress((void**)&hPhB, g_hPhB); cudaGetSymbolAddress((void**)&hPlB, g_hPlB);
    __nv_bfloat16 *Winh, *Winl, *Hdh, *Hdl, *xh, *xl;
    cudaGetSymbolAddress((void**)&Winh, g_Winhi); cudaGetSymbolAddress((void**)&Winl, g_Winlo);
    cudaGetSymbolAddress((void**)&Hdh, g_Hdhi);   cudaGetSymbolAddress((void**)&Hdl, g_Hdlo);
    cudaGetSymbolAddress((void**)&xh, g_xhi);     cudaGetSymbolAddress((void**)&xl, g_xlo);

    cudaFuncSetAttribute(gemm_mma<0, 0>, cudaFuncAttributeMaxDynamicSharedMemorySize, SMEM_BYTES);
    cudaFuncSetAttribute(gemm_mma<2, 1>, cudaFuncAttributeMaxDynamicSharedMemorySize, SMEM_BYTES);
    cudaFuncSetAttribute(gemm_step, cudaFuncAttributeMaxDynamicSharedMemorySize, S_SMEM);

    // 0: prep (splits + packing + zeros + matvec_t + ticket reset)
    prep_kernel<<<592, 256>>>(W0, W1, W2, Winw, headw, x, u);
    // 1: sigma (matvec_s + reduce, ticket-synced)
    sigma_kernel<<<64, 256>>>(Winw, t, s, scal);
    // 2: x_proj (writes xpb[0..2] with per-layer bias folded)
    {
        dim3 grid(D_H / 64, BATCH / 64);
        gemm_mma<0, 0><<<grid, 128, SMEM_BYTES>>>(xh, xl, Winh, Winl, Winb,
                                                  nullptr, scal + 1, D_IN, D_H, D_H,
                                                  b0, b1, b2, xpb);
    }
    // 3..92: 30 steps x 3 layers  — grid (mt, nt) so B-sharing CTAs are adjacent
    const char* Whp[3] = {W0hp, W1hp, W2hp};
    const char* Wlp[3] = {W0lp, W1lp, W2lp};
    float *cur = hA, *nxt = hB;
    char *curh = hPhA, *curl = hPlA, *nxth = hPhB, *nxtl = hPlB;
    dim3 gstep(BATCH / 64, D_H / 64);
    for (int st = 0; st < STEPS; st++) {
        for (int l = 0; l < 3; l++) {
            gemm_step<<<gstep, 256, S_SMEM>>>(curh, curl, Whp[l], Wlp[l],
                                              xpb + (size_t)l * BATCH * D_H,
                                              cur, nxt, nxth, nxtl);
            float* tf = cur; cur = nxt; nxt = tf;
            char* th = curh; curh = nxth; nxth = th;
            char* tl = curl; curl = nxtl; nxtl = tl;
        }
    }
    // 93: head (A = packed final h)
    {
        dim3 grid((D_OUT + 63) / 64, BATCH / 64);
        gemm_mma<2, 1><<<grid, 128, SMEM_BYTES>>>(curh, curl, Hdh, Hdl, headb,
                                                  out, nullptr, D_H, D_OUT, D_OUT,
                                                  nullptr, nullptr, nullptr, nullptr);
    }
}

// round 14
// speedup vs baseline: 1.1064x; 1.1064x over previous
#include <cuda_runtime.h>
#include <cuda_bf16.h>
#include <math.h>
#include <stdint.h>

#define D_IN   1024
#define D_H    2048
#define BATCH  256
#define D_OUT  1000
#define EPSV   1e-12f
#define STEPS  30

// ---- bf16 aux GEMM smem geometry (x_proj / head, 128-thread kernel) ----
#define ROW_B      144
#define TILE_A_HI  0
#define TILE_A_LO  9216
#define TILE_B_HI  18432
#define TILE_B_LO  27648
#define STAGE_BYTES 36864
#define SMEM_BYTES  (2 * STAGE_BYTES)

// ---- step GEMM: CTA tile 64x32, BK=128 panels, 2 stages, 2 CTAs/SM ----
#define SROW     272
#define ATILE    17408                // 64 rows * 272
#define BTILE    8704                 // 32 rows * 272
#define S_AH     0
#define S_AL     17408
#define S_BH     34816
#define S_BL     43520
#define S_STAGE  52224
#define S_DATA   128                  // mbarriers below
#define S_SMEM   (S_DATA + 2 * S_STAGE)   // 104576
#define S_TX     52224

// h (A operand) panels: 64-row x BK=128 blocks (same as R12; head kernel uses this)
#define NKCH     16
__host__ __device__ __forceinline__ size_t pkoff(int r, int k) {
    return ((size_t)((r >> 6) * NKCH + (k >> 7))) * ATILE +
           (size_t)(r & 63) * SROW + (size_t)((k & 127) << 1);
}
// W (B operand) panels: 32-row x BK=128 blocks
__host__ __device__ __forceinline__ size_t pkoffW(int r, int k) {
    return ((size_t)((r >> 5) * NKCH + (k >> 7))) * BTILE +
           (size_t)(r & 31) * SROW + (size_t)((k & 127) << 1);
}

// ---------------- device scratch (no allocations allowed) ----------------
__device__ float g_t[D_IN];
__device__ float g_s[D_H];
__device__ float g_scal[4];              // [1] = 1/sigma
__device__ int   g_ticket;
__device__ float g_xpb[3][BATCH * D_H];  // xproj + bias_l
__device__ float g_hA[BATCH * D_H];
__device__ float g_hB[BATCH * D_H];

#define WPK_BYTES ((size_t)64 * NKCH * BTILE)   // 8,912,896
#define HPK_BYTES ((size_t)4  * NKCH * ATILE)   // 1,114,112
__device__ char g_W0hp[WPK_BYTES], g_W0lp[WPK_BYTES];
__device__ char g_W1hp[WPK_BYTES], g_W1lp[WPK_BYTES];
__device__ char g_W2hp[WPK_BYTES], g_W2lp[WPK_BYTES];
__device__ char g_hPhA[HPK_BYTES], g_hPlA[HPK_BYTES];
__device__ char g_hPhB[HPK_BYTES], g_hPlB[HPK_BYTES];

__device__ __nv_bfloat16 g_Winhi[D_H * D_IN], g_Winlo[D_H * D_IN];
__device__ __nv_bfloat16 g_Hdhi[D_OUT * D_H], g_Hdlo[D_OUT * D_H];
__device__ __nv_bfloat16 g_xhi[BATCH * D_IN], g_xlo[BATCH * D_IN];

// ---------------- portable PTX helpers ----------------
__device__ __forceinline__ uint32_t smem_u32(const void* p) {
    uint32_t a;
    asm("{ .reg .u64 t; cvta.to.shared.u64 t, %1; cvt.u32.u64 %0, t; }" : "=r"(a) : "l"(p));
    return a;
}
#define CP16(dst, src) asm volatile("cp.async.cg.shared.global [%0], [%1], 16;" :: "r"(dst), "l"(src))
#define CP_COMMIT()    asm volatile("cp.async.commit_group;" ::: "memory")
#define CP_WAIT(n)     asm volatile("cp.async.wait_group %0;" :: "n"(n) : "memory")

#define MBAR_INIT(a, c) asm volatile("mbarrier.init.shared.b64 [%0], %1;" :: "r"(a), "r"(c) : "memory")
#define MBAR_EXPECT(a, bytes) \
    asm volatile("mbarrier.arrive.expect_tx.shared.b64 _, [%0], %1;" :: "r"(a), "r"(bytes) : "memory")
#define BULKA(dst, src, mbar) \
    asm volatile("cp.async.bulk.shared::cluster.global.mbarrier::complete_tx::bytes [%0], [%1], 17408, [%2];" \
        :: "r"(dst), "l"(src), "r"(mbar) : "memory")
#define BULKB(dst, src, mbar) \
    asm volatile("cp.async.bulk.shared::cluster.global.mbarrier::complete_tx::bytes [%0], [%1], 8704, [%2];" \
        :: "r"(dst), "l"(src), "r"(mbar) : "memory")
#define MBAR_WAIT(mbar, parity) do {                                              \
    uint32_t _m = (mbar), _p = (parity), _d;                                      \
    asm volatile("{ .reg .pred p; mbarrier.try_wait.parity.acquire.cta.shared::cta.b64 p, [%1], %2; selp.b32 %0, 1, 0, p; }" \
        : "=r"(_d) : "r"(_m), "r"(_p) : "memory");                                \
    if (!_d) {                                                                    \
        asm volatile("{ .reg .pred P1; WL_%=: mbarrier.try_wait.parity.acquire.cta.shared::cta.b64 P1, [%0], %1, 0x989680; @P1 bra.uni WD_%=; bra.uni WL_%=; WD_%=: }" \
            :: "r"(_m), "r"(_p) : "memory");                                      \
    }                                                                             \
} while (0)

__device__ __forceinline__ void ldsm4(uint32_t* r, uint32_t addr) {
    asm volatile("ldmatrix.sync.aligned.m8n8.x4.shared.b16 {%0,%1,%2,%3}, [%4];"
        : "=r"(r[0]), "=r"(r[1]), "=r"(r[2]), "=r"(r[3]) : "r"(addr));
}
__device__ __forceinline__ void mma_bf16(float* c, const uint32_t* a, const uint32_t* b) {
    asm volatile("mma.sync.aligned.m16n8k16.row.col.f32.bf16.bf16.f32 "
        "{%0,%1,%2,%3}, {%4,%5,%6,%7}, {%8,%9}, {%0,%1,%2,%3};"
        : "+f"(c[0]), "+f"(c[1]), "+f"(c[2]), "+f"(c[3])
        : "r"(a[0]), "r"(a[1]), "r"(a[2]), "r"(a[3]), "r"(b[0]), "r"(b[1]));
}

// ---------------- prep: splits + packing + h0 zeros + matvec_t + ticket reset ----
__device__ __forceinline__ void split_plain(const float* __restrict__ src,
        __nv_bfloat16* __restrict__ hi, __nv_bfloat16* __restrict__ lo, int i) {
    float a = src[i];
    __nv_bfloat16 h = __float2bfloat16(a);
    hi[i] = h;
    lo[i] = __float2bfloat16(a - __bfloat162float(h));
}
__device__ __forceinline__ void split_packW(const float* __restrict__ src,
        char* __restrict__ hp, char* __restrict__ lp, int i) {
    const int r = i >> 11, k = i & 2047;
    const size_t off = pkoffW(r, k);
    float a = src[i];
    __nv_bfloat16 h = __float2bfloat16(a);
    *reinterpret_cast<__nv_bfloat16*>(hp + off) = h;
    *reinterpret_cast<__nv_bfloat16*>(lp + off) =
        __float2bfloat16(a - __bfloat162float(h));
}

__global__ void prep_kernel(const float* __restrict__ W0, const float* __restrict__ W1,
                            const float* __restrict__ W2, const float* __restrict__ Win,
                            const float* __restrict__ Hd, const float* __restrict__ x,
                            const float* __restrict__ u) {
    const int stride = gridDim.x * blockDim.x;
    const int t0 = blockIdx.x * blockDim.x + threadIdx.x;
    if (t0 == 0) g_ticket = 0;
    for (int i = t0; i < D_H * D_H; i += stride) {
        split_packW(W0, g_W0hp, g_W0lp, i);
        split_packW(W1, g_W1hp, g_W1lp, i);
        split_packW(W2, g_W2hp, g_W2lp, i);
    }
    for (int i = t0; i < D_H * D_IN; i += stride) split_plain(Win, g_Winhi, g_Winlo, i);
    for (int i = t0; i < D_OUT * D_H; i += stride) split_plain(Hd, g_Hdhi, g_Hdlo, i);
    for (int i = t0; i < BATCH * D_IN; i += stride) split_plain(x, g_xhi, g_xlo, i);
    for (int i = t0; i < BATCH * D_H; i += stride) g_hA[i] = 0.0f;
    for (int i = t0; i < (int)(HPK_BYTES / 4); i += stride) {
        reinterpret_cast<uint32_t*>(g_hPhA)[i] = 0u;
        reinterpret_cast<uint32_t*>(g_hPlA)[i] = 0u;
    }
    for (int j = t0; j < D_IN; j += stride) {
        float acc = 0.0f;
#pragma unroll 4
        for (int i = 0; i < D_H; i++) acc = fmaf(Win[(size_t)i * D_IN + j], u[i], acc);
        g_t[j] = acc;
    }
}

// ---------------- sigma: matvec_s + final reduce, ticket-synced ----------------
__global__ void sigma_kernel(const float* __restrict__ W, const float* __restrict__ t,
                             float* __restrict__ s, float* __restrict__ scal) {
    __shared__ float shw[8];
    __shared__ int lastf;
    const int tid = threadIdx.x;
    const int lane = tid & 31;
    const int w = tid >> 5;
    float ss = 0.0f;
#pragma unroll
    for (int i = 0; i < 4; i++) {
        float v = t[tid + (i << 8)];
        ss = fmaf(v, v, ss);
    }
#pragma unroll
    for (int o = 16; o > 0; o >>= 1) ss += __shfl_xor_sync(0xffffffffu, ss, o);
    if (lane == 0) shw[w] = ss;
    __syncthreads();
    float tot = shw[lane & 7];
#pragma unroll
    for (int o = 4; o > 0; o >>= 1) tot += __shfl_xor_sync(0xffffffffu, tot, o);
    const float invn = 1.0f / (sqrtf(tot) + EPSV);

    const int gwarp = blockIdx.x * 8 + w;
    for (int r = gwarp; r < D_H; r += 512) {
        const float* row = W + (size_t)r * D_IN;
        float acc = 0.0f;
        for (int j = lane; j < D_IN; j += 32) acc = fmaf(row[j], t[j], acc);
#pragma unroll
        for (int o = 16; o > 0; o >>= 1) acc += __shfl_xor_sync(0xffffffffu, acc, o);
        if (lane == 0) s[r] = acc * invn;
    }
    __threadfence();
    if (tid == 0) lastf = (atomicAdd(&g_ticket, 1) == (int)gridDim.x - 1);
    __syncthreads();
    if (lastf) {
        __threadfence();
        float q = 0.0f;
        for (int i = tid; i < D_H; i += 256) { float v = s[i]; q = fmaf(v, v, q); }
#pragma unroll
        for (int o = 16; o > 0; o >>= 1) q += __shfl_xor_sync(0xffffffffu, q, o);
        if (lane == 0) shw[w] = q;
        __syncthreads();
        if (tid == 0) {
            float Q = 0.0f;
#pragma unroll
            for (int i = 0; i < 8; i++) Q += shw[i];
            scal[1] = (sqrtf(Q) + EPSV) / Q;
        }
    }
}

// ================= bf16 3-pass aux GEMM (x_proj MODE 0, head MODE 2) =================
template <int AP>
__device__ __forceinline__ void prefetch_chunk(uint32_t sb_u, char* sb_p, int k0,
        const void* Ahi, const void* Alo,
        const __nv_bfloat16* __restrict__ Bhi, const __nv_bfloat16* __restrict__ Blo,
        int K, int NB, int m0, int n0) {
    const int t = threadIdx.x;
#pragma unroll
    for (int r = 0; r < 4; r++) {
        const int idx = t + (r << 7);
        const int row = idx >> 3;
        const int c   = idx & 7;
        const uint32_t soff = (uint32_t)row * ROW_B + (c << 4);
        const void *pa, *pl;
        if (AP == 0) {
            const size_t ga = (size_t)(m0 + row) * K + k0 + (c << 3);
            pa = (const __nv_bfloat16*)Ahi + ga;
            pl = (const __nv_bfloat16*)Alo + ga;
        } else {
            const size_t gb = ((size_t)((m0 >> 6) * NKCH + (k0 >> 7))) * ATILE +
                              (size_t)row * SROW + ((k0 & 127) << 1) + (c << 4);
            pa = (const char*)Ahi + gb;
            pl = (const char*)Alo + gb;
        }
        CP16(sb_u + TILE_A_HI + soff, pa);
        CP16(sb_u + TILE_A_LO + soff, pl);
        const int gn = n0 + row;
        if (gn < NB) {
            const size_t gb2 = (size_t)gn * K + k0 + (c << 3);
            CP16(sb_u + TILE_B_HI + soff, Bhi + gb2);
            CP16(sb_u + TILE_B_LO + soff, Blo + gb2);
        } else {
            const uint4 z = make_uint4(0, 0, 0, 0);
            *reinterpret_cast<uint4*>(sb_p + TILE_B_HI + soff) = z;
            *reinterpret_cast<uint4*>(sb_p + TILE_B_LO + soff) = z;
        }
    }
}

template <int MODE, int AP>
__global__ void __launch_bounds__(128)
gemm_mma(const void* Ahi, const void* Alo,
         const __nv_bfloat16* __restrict__ Bhi, const __nv_bfloat16* __restrict__ Blo,
         const float* __restrict__ bias, float* __restrict__ outF,
         const float* __restrict__ scale_ptr, int K, int NB, int ldOut,
         const float* __restrict__ lb0, const float* __restrict__ lb1,
         const float* __restrict__ lb2, float* __restrict__ xpb) {
    extern __shared__ char smem[];
    const uint32_t sbase = smem_u32(smem);
    const int tid  = threadIdx.x;
    const int lane = tid & 31;
    const int wid  = tid >> 5;
    const int m0 = blockIdx.y * 64;
    const int n0 = blockIdx.x * 64;
    const int wm = (wid >> 1) << 5;
    const int wn = (wid & 1) << 5;
    const int NC = K >> 6;

    const int arow  = (lane & 7) | (((lane >> 3) & 1) << 3);
    const int akoff = ((lane >> 4) & 1) << 3;
    const int brow  = (lane & 7) | (((lane >> 4) & 1) << 3);
    const int bkoff = ((lane >> 3) & 1) << 3;

    float acc[2][4][4] = {};

    prefetch_chunk<AP>(sbase, smem, 0, Ahi, Alo, Bhi, Blo, K, NB, m0, n0);
    CP_COMMIT();

    for (int c = 0; c < NC; c++) {
        if (c + 1 < NC) {
            const int ns = (c + 1) & 1;
            prefetch_chunk<AP>(sbase + ns * STAGE_BYTES, smem + ns * STAGE_BYTES,
                               (c + 1) << 6, Ahi, Alo, Bhi, Blo, K, NB, m0, n0);
            CP_COMMIT();
            CP_WAIT(1);
        } else {
            CP_WAIT(0);
        }
        __syncthreads();

        const uint32_t st = sbase + (c & 1) * STAGE_BYTES;
#pragma unroll
        for (int kk = 0; kk < 4; kk++) {
            const int k0 = kk << 4;
            uint32_t ah[2][4], al[2][4], bh[2][4], bl[2][4];
#pragma unroll
            for (int a = 0; a < 2; a++) {
                const uint32_t off = (uint32_t)(wm + (a << 4) + arow) * ROW_B +
                                     ((k0 + akoff) << 1);
                ldsm4(ah[a], st + TILE_A_HI + off);
                ldsm4(al[a], st + TILE_A_LO + off);
            }
#pragma unroll
            for (int b = 0; b < 2; b++) {
                const uint32_t off = (uint32_t)(wn + (b << 4) + brow) * ROW_B +
                                     ((k0 + bkoff) << 1);
                ldsm4(bh[b], st + TILE_B_HI + off);
                ldsm4(bl[b], st + TILE_B_LO + off);
            }
#pragma unroll
            for (int a = 0; a < 2; a++)
#pragma unroll
                for (int j = 0; j < 4; j++)
                    mma_bf16(acc[a][j], ah[a], &bh[j >> 1][(j & 1) << 1]);
#pragma unroll
            for (int a = 0; a < 2; a++)
#pragma unroll
                for (int j = 0; j < 4; j++)
                    mma_bf16(acc[a][j], ah[a], &bl[j >> 1][(j & 1) << 1]);
#pragma unroll
            for (int a = 0; a < 2; a++)
#pragma unroll
                for (int j = 0; j < 4; j++)
                    mma_bf16(acc[a][j], al[a], &bh[j >> 1][(j & 1) << 1]);
        }
        __syncthreads();
    }

    const float scale = (MODE == 0) ? *scale_ptr : 1.0f;
    const int g  = lane >> 2;
    const int i2 = (lane & 3) << 1;
#pragma unroll
    for (int a = 0; a < 2; a++)
#pragma unroll
        for (int j = 0; j < 4; j++)
#pragma unroll
            for (int e = 0; e < 4; e++) {
                const int m = m0 + wm + (a << 4) + g + ((e >> 1) << 3);
                const int n = n0 + wn + (j << 3) + i2 + (e & 1);
                const float r = acc[a][j][e];
                if (MODE == 0) {
                    const float v = fmaf(r, scale, bias[n]);
                    const size_t idx = (size_t)m * D_H + n;
                    xpb[idx] = v + lb0[n];
                    xpb[(size_t)BATCH * D_H + idx] = v + lb1[n];
                    xpb[(size_t)2 * BATCH * D_H + idx] = v + lb2[n];
                } else {
                    if (n < NB) outF[(size_t)m * ldOut + n] = r + bias[n];
                }
            }
}

// ====== step GEMM: 64x32 CTA tile, 4 warps (2 out x 2 split-K), 2 CTAs/SM ======
__device__ __forceinline__ void issue_chunk(uint32_t st_u, uint32_t mbar, int chunk,
        const char* __restrict__ AH, const char* __restrict__ AL,
        const char* __restrict__ BH, const char* __restrict__ BL, int mt, int nt) {
    const size_t ab = ((size_t)(mt * NKCH + chunk)) * ATILE;
    const size_t bb = ((size_t)(nt * NKCH + chunk)) * BTILE;
    BULKA(st_u + S_AH, AH + ab, mbar);
    BULKA(st_u + S_AL, AL + ab, mbar);
    BULKB(st_u + S_BH, BH + bb, mbar);
    BULKB(st_u + S_BL, BL + bb, mbar);
}

__global__ void __launch_bounds__(128)
gemm_step(const char* __restrict__ AH, const char* __restrict__ AL,
          const char* __restrict__ BH, const char* __restrict__ BL,
          const float* __restrict__ xpb, const float* __restrict__ hold,
          float* __restrict__ outF,
          char* __restrict__ outHp, char* __restrict__ outLp) {
    extern __shared__ char smem[];
    const uint32_t sbase = smem_u32(smem);
    const uint32_t data0 = sbase + S_DATA;
    const int tid  = threadIdx.x;
    const int lane = tid & 31;
    const int wid  = tid >> 5;
    const int wk   = wid & 1;         // split-K half
    const int wq   = wid >> 1;        // 0..1 output m-half
    const int nt = blockIdx.x;        // 0..63  (B 32-row tile)
    const int mt = blockIdx.y;        // 0..3   (A 64-row tile)
    const int m0 = mt << 6;
    const int n0 = nt << 5;
    const int wm = wq << 5;
    const int NC = NKCH;              // 16 chunks of 128

    const int arow  = (lane & 7) | (((lane >> 3) & 1) << 3);
    const int akoff = ((lane >> 4) & 1) << 3;
    const int brow  = (lane & 7) | (((lane >> 4) & 1) << 3);
    const int bkoff = ((lane >> 3) & 1) << 3;
    const int kbase = wk << 2;        // kk 0-3 or 4-7

    float accm[2][4][4] = {};
    float acc1[2][4][4] = {};
    float acc2[2][4][4] = {};

    if (tid == 0) { MBAR_INIT(sbase + 0, 1); MBAR_INIT(sbase + 16, 1); }
    __syncthreads();
    if (tid == 0) {
        MBAR_EXPECT(sbase + 0, S_TX);
        issue_chunk(data0, sbase + 0, 0, AH, AL, BH, BL, mt, nt);
    }

    for (int c = 0; c < NC; c++) {
        const int s = c & 1;
        if (c + 1 < NC) {
            __syncthreads();   // all warps done reading stage s^1 (chunk c-1)
            if (tid == 0) {
                MBAR_EXPECT(sbase + ((s ^ 1) << 4), S_TX);
                issue_chunk(data0 + (s ^ 1) * S_STAGE, sbase + ((s ^ 1) << 4), c + 1,
                            AH, AL, BH, BL, mt, nt);
            }
        }
        MBAR_WAIT(sbase + (s << 4), (c >> 1) & 1);

        const uint32_t st = data0 + s * S_STAGE;
#pragma unroll
        for (int kki = 0; kki < 4; kki++) {
            const int k0 = (kbase + kki) << 4;
            uint32_t ah[2][4], al[2][4], bh[2][4], bl[2][4];
#pragma unroll
            for (int a = 0; a < 2; a++) {
                const uint32_t off = (uint32_t)(wm + (a << 4) + arow) * SROW +
                                     ((k0 + akoff) << 1);
                ldsm4(ah[a], st + S_AH + off);
                ldsm4(al[a], st + S_AL + off);
            }
#pragma unroll
            for (int b = 0; b < 2; b++) {
                const uint32_t off = (uint32_t)((b << 4) + brow) * SROW +
                                     ((k0 + bkoff) << 1);
                ldsm4(bh[b], st + S_BH + off);
                ldsm4(bl[b], st + S_BL + off);
            }
#pragma unroll
            for (int a = 0; a < 2; a++)
#pragma unroll
                for (int j = 0; j < 4; j++) {
                    mma_bf16(accm[a][j], ah[a], &bh[j >> 1][(j & 1) << 1]);
                    mma_bf16(acc1[a][j], ah[a], &bl[j >> 1][(j & 1) << 1]);
                    mma_bf16(acc2[a][j], al[a], &bh[j >> 1][(j & 1) << 1]);
                }
        }
    }

    // local 3-bank reduce
    float rsum[2][4][4];
#pragma unroll
    for (int a = 0; a < 2; a++)
#pragma unroll
        for (int j = 0; j < 4; j++)
#pragma unroll
            for (int e = 0; e < 4; e++)
                rsum[a][j][e] = accm[a][j][e] + acc1[a][j][e] + acc2[a][j][e];

    // cross-warp split-K reduction via (now dead) stage smem
    __syncthreads();
    float* red = reinterpret_cast<float*>(smem + S_DATA);
    if (wk == 1) {
        float* dst = red + (wq << 10);
#pragma unroll
        for (int a = 0; a < 2; a++)
#pragma unroll
            for (int j = 0; j < 4; j++)
#pragma unroll
                for (int e = 0; e < 4; e++)
                    dst[((a << 4) | (j << 2) | e) << 5 | lane] = rsum[a][j][e];
    }
    __syncthreads();
    if (wk == 0) {
        const float* src = red + (wq << 10);
#pragma unroll
        for (int a = 0; a < 2; a++)
#pragma unroll
            for (int j = 0; j < 4; j++)
#pragma unroll
                for (int e = 0; e < 4; e++)
                    rsum[a][j][e] += src[((a << 4) | (j << 2) | e) << 5 | lane];

        // epilogue: fp32 h (plain) + bf16 hi/lo limbs (packed 64-row panels)
        const int g  = lane >> 2;
        const int i2 = (lane & 3) << 1;
#pragma unroll
        for (int a = 0; a < 2; a++)
#pragma unroll
            for (int j = 0; j < 4; j++)
#pragma unroll
                for (int eh = 0; eh < 2; eh++) {
                    const int m = m0 + wm + (a << 4) + g + (eh << 3);
                    const int n = n0 + (j << 3) + i2;
                    const size_t idx = (size_t)m * D_H + n;
                    const float r0 = rsum[a][j][eh * 2 + 0];
                    const float r1 = rsum[a][j][eh * 2 + 1];
                    const float2 xb = *reinterpret_cast<const float2*>(xpb + idx);
                    const float2 ho = *reinterpret_cast<const float2*>(hold + idx);
                    const float hn0 = 0.5f * ho.x + 0.5f * tanhf(xb.x + r0);
                    const float hn1 = 0.5f * ho.y + 0.5f * tanhf(xb.y + r1);
                    *reinterpret_cast<float2*>(outF + idx) = make_float2(hn0, hn1);
                    const __nv_bfloat16 b0 = __float2bfloat16(hn0);
                    const __nv_bfloat16 b1 = __float2bfloat16(hn1);
                    __nv_bfloat162 hiv, lov;
                    hiv.x = b0; hiv.y = b1;
                    lov.x = __float2bfloat16(hn0 - __bfloat162float(b0));
                    lov.y = __float2bfloat16(hn1 - __bfloat162float(b1));
                    const size_t pidx = pkoff(m, n);
                    *reinterpret_cast<__nv_bfloat162*>(outHp + pidx) = hiv;
                    *reinterpret_cast<__nv_bfloat162*>(outLp + pidx) = lov;
                }
    }
}

// ---------------- host ----------------
extern "C" void kernel_launch(void* const* d_in, const int* in_sizes, int n_in,
                              void* d_out, int out_size) {
    const float* x     = (const float*)d_in[0];
    const float* Winw  = (const float*)d_in[1];
    const float* Winb  = (const float*)d_in[2];
    const float* u     = (const float*)d_in[3];
    const float* W0    = (const float*)d_in[4];
    const float* b0    = (const float*)d_in[5];
    const float* W1    = (const float*)d_in[6];
    const float* b1    = (const float*)d_in[7];
    const float* W2    = (const float*)d_in[8];
    const float* b2    = (const float*)d_in[9];
    const float* headw = (const float*)d_in[10];
    const float* headb = (const float*)d_in[11];
    float* out = (float*)d_out;

    float *t, *s, *scal, *hA, *hB, *xpb;
    cudaGetSymbolAddress((void**)&t, g_t);
    cudaGetSymbolAddress((void**)&s, g_s);
    cudaGetSymbolAddress((void**)&scal, g_scal);
    cudaGetSymbolAddress((void**)&xpb, g_xpb);
    cudaGetSymbolAddress((void**)&hA, g_hA);
    cudaGetSymbolAddress((void**)&hB, g_hB);
    char *W0hp, *W0lp, *W1hp, *W1lp, *W2hp, *W2lp, *hPhA, *hPlA, *hPhB, *hPlB;
    cudaGetSymbolAddress((void**)&W0hp, g_W0hp); cudaGetSymbolAddress((void**)&W0lp, g_W0lp);
    cudaGetSymbolAddress((void**)&W1hp, g_W1hp); cudaGetSymbolAddress((void**)&W1lp, g_W1lp);
    cudaGetSymbolAddress((void**)&W2hp, g_W2hp); cudaGetSymbolAddress((void**)&W2lp, g_W2lp);
    cudaGetSymbolAddress((void**)&hPhA, g_hPhA); cudaGetSymbolAddress((void**)&hPlA, g_hPlA);
    cudaGetSymbolAddress((void**)&hPhB, g_hPhB); cudaGetSymbolAddress((void**)&hPlB, g_hPlB);
    __nv_bfloat16 *Winh, *Winl, *Hdh, *Hdl, *xh, *xl;
    cudaGetSymbolAddress((void**)&Winh, g_Winhi); cudaGetSymbolAddress((void**)&Winl, g_Winlo);
    cudaGetSymbolAddress((void**)&Hdh, g_Hdhi);   cudaGetSymbolAddress((void**)&Hdl, g_Hdlo);
    cudaGetSymbolAddress((void**)&xh, g_xhi);     cudaGetSymbolAddress((void**)&xl, g_xlo);

    cudaFuncSetAttribute(gemm_mma<0, 0>, cudaFuncAttributeMaxDynamicSharedMemorySize, SMEM_BYTES);
    cudaFuncSetAttribute(gemm_mma<2, 1>, cudaFuncAttributeMaxDynamicSharedMemorySize, SMEM_BYTES);
    cudaFuncSetAttribute(gemm_step, cudaFuncAttributeMaxDynamicSharedMemorySize, S_SMEM);

    // 0: prep (splits + packing + zeros + matvec_t + ticket reset)
    prep_kernel<<<592, 256>>>(W0, W1, W2, Winw, headw, x, u);
    // 1: sigma (matvec_s + reduce, ticket-synced)
    sigma_kernel<<<64, 256>>>(Winw, t, s, scal);
    // 2: x_proj (writes xpb[0..2] with per-layer bias folded)
    {
        dim3 grid(D_H / 64, BATCH / 64);
        gemm_mma<0, 0><<<grid, 128, SMEM_BYTES>>>(xh, xl, Winh, Winl, Winb,
                                                  nullptr, scal + 1, D_IN, D_H, D_H,
                                                  b0, b1, b2, xpb);
    }
    // 3..92: 30 steps x 3 layers — 256 CTAs (2/SM), 64x32 tiles
    const char* Whp[3] = {W0hp, W1hp, W2hp};
    const char* Wlp[3] = {W0lp, W1lp, W2lp};
    float *cur = hA, *nxt = hB;
    char *curh = hPhA, *curl = hPlA, *nxth = hPhB, *nxtl = hPlB;
    dim3 gstep(D_H / 32, BATCH / 64);
    for (int st = 0; st < STEPS; st++) {
        for (int l = 0; l < 3; l++) {
            gemm_step<<<gstep, 128, S_SMEM>>>(curh, curl, Whp[l], Wlp[l],
                                              xpb + (size_t)l * BATCH * D_H,
                                              cur, nxt, nxth, nxtl);
            float* tf = cur; cur = nxt; nxt = tf;
            char* th = curh; curh = nxth; nxth = th;
            char* tl = curl; curl = nxtl; nxtl = tl;
        }
    }
    // 93: head (A = packed final h)
    {
        dim3 grid((D_OUT + 63) / 64, BATCH / 64);
        gemm_mma<2, 1><<<grid, 128, SMEM_BYTES>>>(curh, curl, Hdh, Hdl, headb,
                                                  out, nullptr, D_H, D_OUT, D_OUT,
                                                  nullptr, nullptr, nullptr, nullptr);
    }
}

// round 15
// speedup vs baseline: 1.1782x; 1.0649x over previous
#include <cuda_runtime.h>
#include <cuda_bf16.h>
#include <math.h>
#include <stdint.h>

#define D_IN   1024
#define D_H    2048
#define BATCH  256
#define D_OUT  1000
#define EPSV   1e-12f
#define STEPS  30
#define NLAUNCH (3 * STEPS)

// ---- bf16 aux GEMM smem geometry (x_proj / head, 128-thread kernel) ----
#define ROW_B      144
#define TILE_A_HI  0
#define TILE_A_LO  9216
#define TILE_B_HI  18432
#define TILE_B_LO  27648
#define STAGE_BYTES 36864
#define SMEM_BYTES  (2 * STAGE_BYTES)

// ---- step GEMM: CTA tile 64x32, BK=128 panels, 2 stages, 2 CTAs/SM ----
#define SROW     272
#define ATILE    17408                // 64 rows * 272
#define BTILE    8704                 // 32 rows * 272
#define S_AH     0
#define S_AL     17408
#define S_BH     34816
#define S_BL     43520
#define S_STAGE  52224
#define S_DATA   128
#define S_SMEM   (S_DATA + 2 * S_STAGE)   // 104576

#define NKCH     16
__host__ __device__ __forceinline__ size_t pkoff(int r, int k) {
    return ((size_t)((r >> 6) * NKCH + (k >> 7))) * ATILE +
           (size_t)(r & 63) * SROW + (size_t)((k & 127) << 1);
}
__host__ __device__ __forceinline__ size_t pkoffW(int r, int k) {
    return ((size_t)((r >> 5) * NKCH + (k >> 7))) * BTILE +
           (size_t)(r & 31) * SROW + (size_t)((k & 127) << 1);
}

// ---------------- device scratch ----------------
__device__ float g_t[D_IN];
__device__ float g_s[D_H];
__device__ float g_scal[4];              // [1] = 1/sigma
__device__ int   g_ticket;
__device__ float g_xpb[3][BATCH * D_H];  // xproj + bias_l
__device__ float g_S[3][BATCH * D_H];    // running W_l . h accumulators
__device__ float g_hring[4][BATCH * D_H];// h output ring
__device__ float g_maxd[NLAUNCH + 2];    // per-launch max |delta|

#define WPK_BYTES ((size_t)64 * NKCH * BTILE)
#define HPK_BYTES ((size_t)4  * NKCH * ATILE)
__device__ char g_W0hp[WPK_BYTES], g_W0lp[WPK_BYTES];
__device__ char g_W1hp[WPK_BYTES], g_W1lp[WPK_BYTES];
__device__ char g_W2hp[WPK_BYTES], g_W2lp[WPK_BYTES];
__device__ char g_dPhA[HPK_BYTES], g_dPlA[HPK_BYTES];   // delta limb ping-pong
__device__ char g_dPhB[HPK_BYTES], g_dPlB[HPK_BYTES];
__device__ char g_hPh[HPK_BYTES], g_hPl[HPK_BYTES];     // final h limbs (head)

__device__ __nv_bfloat16 g_Winhi[D_H * D_IN], g_Winlo[D_H * D_IN];
__device__ __nv_bfloat16 g_Hdhi[D_OUT * D_H], g_Hdlo[D_OUT * D_H];
__device__ __nv_bfloat16 g_xhi[BATCH * D_IN], g_xlo[BATCH * D_IN];

// ---------------- portable PTX helpers ----------------
__device__ __forceinline__ uint32_t smem_u32(const void* p) {
    uint32_t a;
    asm("{ .reg .u64 t; cvta.to.shared.u64 t, %1; cvt.u32.u64 %0, t; }" : "=r"(a) : "l"(p));
    return a;
}
#define CP16(dst, src) asm volatile("cp.async.cg.shared.global [%0], [%1], 16;" :: "r"(dst), "l"(src))
#define CP_COMMIT()    asm volatile("cp.async.commit_group;" ::: "memory")
#define CP_WAIT(n)     asm volatile("cp.async.wait_group %0;" :: "n"(n) : "memory")

#define MBAR_INIT(a, c) asm volatile("mbarrier.init.shared.b64 [%0], %1;" :: "r"(a), "r"(c) : "memory")
#define MBAR_EXPECT(a, bytes) \
    asm volatile("mbarrier.arrive.expect_tx.shared.b64 _, [%0], %1;" :: "r"(a), "r"(bytes) : "memory")
#define BULKA(dst, src, mbar) \
    asm volatile("cp.async.bulk.shared::cluster.global.mbarrier::complete_tx::bytes [%0], [%1], 17408, [%2];" \
        :: "r"(dst), "l"(src), "r"(mbar) : "memory")
#define BULKB(dst, src, mbar) \
    asm volatile("cp.async.bulk.shared::cluster.global.mbarrier::complete_tx::bytes [%0], [%1], 8704, [%2];" \
        :: "r"(dst), "l"(src), "r"(mbar) : "memory")
#define MBAR_WAIT(mbar, parity) do {                                              \
    uint32_t _m = (mbar), _p = (parity), _d;                                      \
    asm volatile("{ .reg .pred p; mbarrier.try_wait.parity.acquire.cta.shared::cta.b64 p, [%1], %2; selp.b32 %0, 1, 0, p; }" \
        : "=r"(_d) : "r"(_m), "r"(_p) : "memory");                                \
    if (!_d) {                                                                    \
        asm volatile("{ .reg .pred P1; WL_%=: mbarrier.try_wait.parity.acquire.cta.shared::cta.b64 P1, [%0], %1, 0x989680; @P1 bra.uni WD_%=; bra.uni WL_%=; WD_%=: }" \
            :: "r"(_m), "r"(_p) : "memory");                                      \
    }                                                                             \
} while (0)

__device__ __forceinline__ void ldsm4(uint32_t* r, uint32_t addr) {
    asm volatile("ldmatrix.sync.aligned.m8n8.x4.shared.b16 {%0,%1,%2,%3}, [%4];"
        : "=r"(r[0]), "=r"(r[1]), "=r"(r[2]), "=r"(r[3]) : "r"(addr));
}
__device__ __forceinline__ void mma_bf16(float* c, const uint32_t* a, const uint32_t* b) {
    asm volatile("mma.sync.aligned.m16n8k16.row.col.f32.bf16.bf16.f32 "
        "{%0,%1,%2,%3}, {%4,%5,%6,%7}, {%8,%9}, {%0,%1,%2,%3};"
        : "+f"(c[0]), "+f"(c[1]), "+f"(c[2]), "+f"(c[3])
        : "r"(a[0]), "r"(a[1]), "r"(a[2]), "r"(a[3]), "r"(b[0]), "r"(b[1]));
}

// ---------------- prep ----------------
__device__ __forceinline__ void split_plain(const float* __restrict__ src,
        __nv_bfloat16* __restrict__ hi, __nv_bfloat16* __restrict__ lo, int i) {
    float a = src[i];
    __nv_bfloat16 h = __float2bfloat16(a);
    hi[i] = h;
    lo[i] = __float2bfloat16(a - __bfloat162float(h));
}
__device__ __forceinline__ void split_packW(const float* __restrict__ src,
        char* __restrict__ hp, char* __restrict__ lp, int i) {
    const int r = i >> 11, k = i & 2047;
    const size_t off = pkoffW(r, k);
    float a = src[i];
    __nv_bfloat16 h = __float2bfloat16(a);
    *reinterpret_cast<__nv_bfloat16*>(hp + off) = h;
    *reinterpret_cast<__nv_bfloat16*>(lp + off) =
        __float2bfloat16(a - __bfloat162float(h));
}

__global__ void prep_kernel(const float* __restrict__ W0, const float* __restrict__ W1,
                            const float* __restrict__ W2, const float* __restrict__ Win,
                            const float* __restrict__ Hd, const float* __restrict__ x,
                            const float* __restrict__ u) {
    const int stride = gridDim.x * blockDim.x;
    const int t0 = blockIdx.x * blockDim.x + threadIdx.x;
    if (t0 == 0) g_ticket = 0;
    for (int i = t0; i < NLAUNCH + 2; i += stride) g_maxd[i] = 0.0f;
    for (int i = t0; i < D_H * D_H; i += stride) {
        split_packW(W0, g_W0hp, g_W0lp, i);
        split_packW(W1, g_W1hp, g_W1lp, i);
        split_packW(W2, g_W2hp, g_W2lp, i);
    }
    for (int i = t0; i < D_H * D_IN; i += stride) split_plain(Win, g_Winhi, g_Winlo, i);
    for (int i = t0; i < D_OUT * D_H; i += stride) split_plain(Hd, g_Hdhi, g_Hdlo, i);
    for (int i = t0; i < BATCH * D_IN; i += stride) split_plain(x, g_xhi, g_xlo, i);
    for (int i = t0; i < BATCH * D_H; i += stride) {
        g_S[0][i] = 0.0f; g_S[1][i] = 0.0f; g_S[2][i] = 0.0f;
        g_hring[0][i] = 0.0f; g_hring[1][i] = 0.0f;
        g_hring[2][i] = 0.0f; g_hring[3][i] = 0.0f;
    }
    for (int i = t0; i < (int)(HPK_BYTES / 4); i += stride) {
        reinterpret_cast<uint32_t*>(g_dPhA)[i] = 0u;
        reinterpret_cast<uint32_t*>(g_dPlA)[i] = 0u;
    }
    for (int j = t0; j < D_IN; j += stride) {
        float acc = 0.0f;
#pragma unroll 4
        for (int i = 0; i < D_H; i++) acc = fmaf(Win[(size_t)i * D_IN + j], u[i], acc);
        g_t[j] = acc;
    }
}

// ---------------- sigma ----------------
__global__ void sigma_kernel(const float* __restrict__ W, const float* __restrict__ t,
                             float* __restrict__ s, float* __restrict__ scal) {
    __shared__ float shw[8];
    __shared__ int lastf;
    const int tid = threadIdx.x;
    const int lane = tid & 31;
    const int w = tid >> 5;
    float ss = 0.0f;
#pragma unroll
    for (int i = 0; i < 4; i++) {
        float v = t[tid + (i << 8)];
        ss = fmaf(v, v, ss);
    }
#pragma unroll
    for (int o = 16; o > 0; o >>= 1) ss += __shfl_xor_sync(0xffffffffu, ss, o);
    if (lane == 0) shw[w] = ss;
    __syncthreads();
    float tot = shw[lane & 7];
#pragma unroll
    for (int o = 4; o > 0; o >>= 1) tot += __shfl_xor_sync(0xffffffffu, tot, o);
    const float invn = 1.0f / (sqrtf(tot) + EPSV);

    const int gwarp = blockIdx.x * 8 + w;
    for (int r = gwarp; r < D_H; r += 512) {
        const float* row = W + (size_t)r * D_IN;
        float acc = 0.0f;
        for (int j = lane; j < D_IN; j += 32) acc = fmaf(row[j], t[j], acc);
#pragma unroll
        for (int o = 16; o > 0; o >>= 1) acc += __shfl_xor_sync(0xffffffffu, acc, o);
        if (lane == 0) s[r] = acc * invn;
    }
    __threadfence();
    if (tid == 0) lastf = (atomicAdd(&g_ticket, 1) == (int)gridDim.x - 1);
    __syncthreads();
    if (lastf) {
        __threadfence();
        float q = 0.0f;
        for (int i = tid; i < D_H; i += 256) { float v = s[i]; q = fmaf(v, v, q); }
#pragma unroll
        for (int o = 16; o > 0; o >>= 1) q += __shfl_xor_sync(0xffffffffu, q, o);
        if (lane == 0) shw[w] = q;
        __syncthreads();
        if (tid == 0) {
            float Q = 0.0f;
#pragma unroll
            for (int i = 0; i < 8; i++) Q += shw[i];
            scal[1] = (sqrtf(Q) + EPSV) / Q;
        }
    }
}

// ================= bf16 3-pass aux GEMM (x_proj MODE 0, head MODE 2) =================
template <int AP>
__device__ __forceinline__ void prefetch_chunk(uint32_t sb_u, char* sb_p, int k0,
        const void* Ahi, const void* Alo,
        const __nv_bfloat16* __restrict__ Bhi, const __nv_bfloat16* __restrict__ Blo,
        int K, int NB, int m0, int n0) {
    const int t = threadIdx.x;
#pragma unroll
    for (int r = 0; r < 4; r++) {
        const int idx = t + (r << 7);
        const int row = idx >> 3;
        const int c   = idx & 7;
        const uint32_t soff = (uint32_t)row * ROW_B + (c << 4);
        const void *pa, *pl;
        if (AP == 0) {
            const size_t ga = (size_t)(m0 + row) * K + k0 + (c << 3);
            pa = (const __nv_bfloat16*)Ahi + ga;
            pl = (const __nv_bfloat16*)Alo + ga;
        } else {
            const size_t gb = ((size_t)((m0 >> 6) * NKCH + (k0 >> 7))) * ATILE +
                              (size_t)row * SROW + ((k0 & 127) << 1) + (c << 4);
            pa = (const char*)Ahi + gb;
            pl = (const char*)Alo + gb;
        }
        CP16(sb_u + TILE_A_HI + soff, pa);
        CP16(sb_u + TILE_A_LO + soff, pl);
        const int gn = n0 + row;
        if (gn < NB) {
            const size_t gb2 = (size_t)gn * K + k0 + (c << 3);
            CP16(sb_u + TILE_B_HI + soff, Bhi + gb2);
            CP16(sb_u + TILE_B_LO + soff, Blo + gb2);
        } else {
            const uint4 z = make_uint4(0, 0, 0, 0);
            *reinterpret_cast<uint4*>(sb_p + TILE_B_HI + soff) = z;
            *reinterpret_cast<uint4*>(sb_p + TILE_B_LO + soff) = z;
        }
    }
}

template <int MODE, int AP>
__global__ void __launch_bounds__(128)
gemm_mma(const void* Ahi, const void* Alo,
         const __nv_bfloat16* __restrict__ Bhi, const __nv_bfloat16* __restrict__ Blo,
         const float* __restrict__ bias, float* __restrict__ outF,
         const float* __restrict__ scale_ptr, int K, int NB, int ldOut,
         const float* __restrict__ lb0, const float* __restrict__ lb1,
         const float* __restrict__ lb2, float* __restrict__ xpb) {
    extern __shared__ char smem[];
    const uint32_t sbase = smem_u32(smem);
    const int tid  = threadIdx.x;
    const int lane = tid & 31;
    const int wid  = tid >> 5;
    const int m0 = blockIdx.y * 64;
    const int n0 = blockIdx.x * 64;
    const int wm = (wid >> 1) << 5;
    const int wn = (wid & 1) << 5;
    const int NC = K >> 6;

    const int arow  = (lane & 7) | (((lane >> 3) & 1) << 3);
    const int akoff = ((lane >> 4) & 1) << 3;
    const int brow  = (lane & 7) | (((lane >> 4) & 1) << 3);
    const int bkoff = ((lane >> 3) & 1) << 3;

    float acc[2][4][4] = {};

    prefetch_chunk<AP>(sbase, smem, 0, Ahi, Alo, Bhi, Blo, K, NB, m0, n0);
    CP_COMMIT();

    for (int c = 0; c < NC; c++) {
        if (c + 1 < NC) {
            const int ns = (c + 1) & 1;
            prefetch_chunk<AP>(sbase + ns * STAGE_BYTES, smem + ns * STAGE_BYTES,
                               (c + 1) << 6, Ahi, Alo, Bhi, Blo, K, NB, m0, n0);
            CP_COMMIT();
            CP_WAIT(1);
        } else {
            CP_WAIT(0);
        }
        __syncthreads();

        const uint32_t st = sbase + (c & 1) * STAGE_BYTES;
#pragma unroll
        for (int kk = 0; kk < 4; kk++) {
            const int k0 = kk << 4;
            uint32_t ah[2][4], al[2][4], bh[2][4], bl[2][4];
#pragma unroll
            for (int a = 0; a < 2; a++) {
                const uint32_t off = (uint32_t)(wm + (a << 4) + arow) * ROW_B +
                                     ((k0 + akoff) << 1);
                ldsm4(ah[a], st + TILE_A_HI + off);
                ldsm4(al[a], st + TILE_A_LO + off);
            }
#pragma unroll
            for (int b = 0; b < 2; b++) {
                const uint32_t off = (uint32_t)(wn + (b << 4) + brow) * ROW_B +
                                     ((k0 + bkoff) << 1);
                ldsm4(bh[b], st + TILE_B_HI + off);
                ldsm4(bl[b], st + TILE_B_LO + off);
            }
#pragma unroll
            for (int a = 0; a < 2; a++)
#pragma unroll
                for (int j = 0; j < 4; j++)
                    mma_bf16(acc[a][j], ah[a], &bh[j >> 1][(j & 1) << 1]);
#pragma unroll
            for (int a = 0; a < 2; a++)
#pragma unroll
                for (int j = 0; j < 4; j++)
                    mma_bf16(acc[a][j], ah[a], &bl[j >> 1][(j & 1) << 1]);
#pragma unroll
            for (int a = 0; a < 2; a++)
#pragma unroll
                for (int j = 0; j < 4; j++)
                    mma_bf16(acc[a][j], al[a], &bh[j >> 1][(j & 1) << 1]);
        }
        __syncthreads();
    }

    const float scale = (MODE == 0) ? *scale_ptr : 1.0f;
    const int g  = lane >> 2;
    const int i2 = (lane & 3) << 1;
#pragma unroll
    for (int a = 0; a < 2; a++)
#pragma unroll
        for (int j = 0; j < 4; j++)
#pragma unroll
            for (int e = 0; e < 4; e++) {
                const int m = m0 + wm + (a << 4) + g + ((e >> 1) << 3);
                const int n = n0 + wn + (j << 3) + i2 + (e & 1);
                const float r = acc[a][j][e];
                if (MODE == 0) {
                    const float v = fmaf(r, scale, bias[n]);
                    const size_t idx = (size_t)m * D_H + n;
                    xpb[idx] = v + lb0[n];
                    xpb[(size_t)BATCH * D_H + idx] = v + lb1[n];
                    xpb[(size_t)2 * BATCH * D_H + idx] = v + lb2[n];
                } else {
                    if (n < NB) outF[(size_t)m * ldOut + n] = r + bias[n];
                }
            }
}

// ====== step GEMM: delta-form, adaptive pass count, 64x32 tile, 2 CTAs/SM ======
__global__ void __launch_bounds__(128)
gemm_step(const char* __restrict__ dAH, const char* __restrict__ dAL,
          const char* __restrict__ WH, const char* __restrict__ WL,
          const float* __restrict__ xpb, float* __restrict__ Sacc,
          const float* __restrict__ hold, const float* __restrict__ h3,
          float* __restrict__ outF,
          char* __restrict__ dNxtH, char* __restrict__ dNxtL,
          char* __restrict__ hPh, char* __restrict__ hPl,
          float* __restrict__ maxd, int lidx) {
    extern __shared__ char smem[];
    const uint32_t sbase = smem_u32(smem);
    const uint32_t data0 = sbase + S_DATA;
    const int tid  = threadIdx.x;
    const int lane = tid & 31;
    const int wid  = tid >> 5;
    const int wk   = wid & 1;
    const int wq   = wid >> 1;
    const int nt = blockIdx.x;
    const int mt = blockIdx.y;
    const int m0 = mt << 6;
    const int n0 = nt << 5;
    const int wm = wq << 5;
    const int NC = NKCH;

    // adaptive pass count from previous launch's max |delta|
    const float md = __ldg(&maxd[lidx]);
    const int p3 = (md >= 1e-2f);
    const int p2 = (md >= 5e-4f);
    const uint32_t tx = 17408u + 8704u + (p2 ? 8704u : 0u) + (p3 ? 17408u : 0u);

    const int arow  = (lane & 7) | (((lane >> 3) & 1) << 3);
    const int akoff = ((lane >> 4) & 1) << 3;
    const int brow  = (lane & 7) | (((lane >> 4) & 1) << 3);
    const int bkoff = ((lane >> 3) & 1) << 3;
    const int kbase = wk << 2;

    float accm[2][4][4] = {};
    float acc1[2][4][4] = {};
    float acc2[2][4][4] = {};

    if (tid == 0) { MBAR_INIT(sbase + 0, 1); MBAR_INIT(sbase + 16, 1); }
    __syncthreads();
    if (tid == 0) {
        MBAR_EXPECT(sbase + 0, tx);
        const size_t ab = ((size_t)(mt * NKCH)) * ATILE;
        const size_t bb = ((size_t)(nt * NKCH)) * BTILE;
        BULKA(data0 + S_AH, dAH + ab, sbase + 0);
        if (p3) BULKA(data0 + S_AL, dAL + ab, sbase + 0);
        BULKB(data0 + S_BH, WH + bb, sbase + 0);
        if (p2) BULKB(data0 + S_BL, WL + bb, sbase + 0);
    }

    for (int c = 0; c < NC; c++) {
        const int s = c & 1;
        if (c + 1 < NC) {
            __syncthreads();
            if (tid == 0) {
                const uint32_t mb = sbase + ((s ^ 1) << 4);
                const uint32_t dst = data0 + (s ^ 1) * S_STAGE;
                MBAR_EXPECT(mb, tx);
                const size_t ab = ((size_t)(mt * NKCH + c + 1)) * ATILE;
                const size_t bb = ((size_t)(nt * NKCH + c + 1)) * BTILE;
                BULKA(dst + S_AH, dAH + ab, mb);
                if (p3) BULKA(dst + S_AL, dAL + ab, mb);
                BULKB(dst + S_BH, WH + bb, mb);
                if (p2) BULKB(dst + S_BL, WL + bb, mb);
            }
        }
        MBAR_WAIT(sbase + (s << 4), (c >> 1) & 1);

        const uint32_t st = data0 + s * S_STAGE;
#pragma unroll
        for (int kki = 0; kki < 4; kki++) {
            const int k0 = (kbase + kki) << 4;
            uint32_t ah[2][4], al[2][4], bh[2][4], bl[2][4];
#pragma unroll
            for (int a = 0; a < 2; a++) {
                const uint32_t off = (uint32_t)(wm + (a << 4) + arow) * SROW +
                                     ((k0 + akoff) << 1);
                ldsm4(ah[a], st + S_AH + off);
            }
            if (p3)
#pragma unroll
                for (int a = 0; a < 2; a++) {
                    const uint32_t off = (uint32_t)(wm + (a << 4) + arow) * SROW +
                                         ((k0 + akoff) << 1);
                    ldsm4(al[a], st + S_AL + off);
                }
#pragma unroll
            for (int b = 0; b < 2; b++) {
                const uint32_t off = (uint32_t)((b << 4) + brow) * SROW +
                                     ((k0 + bkoff) << 1);
                ldsm4(bh[b], st + S_BH + off);
            }
            if (p2)
#pragma unroll
                for (int b = 0; b < 2; b++) {
                    const uint32_t off = (uint32_t)((b << 4) + brow) * SROW +
                                         ((k0 + bkoff) << 1);
                    ldsm4(bl[b], st + S_BL + off);
                }
#pragma unroll
            for (int a = 0; a < 2; a++)
#pragma unroll
                for (int j = 0; j < 4; j++)
                    mma_bf16(accm[a][j], ah[a], &bh[j >> 1][(j & 1) << 1]);
            if (p2)
#pragma unroll
                for (int a = 0; a < 2; a++)
#pragma unroll
                    for (int j = 0; j < 4; j++)
                        mma_bf16(acc1[a][j], ah[a], &bl[j >> 1][(j & 1) << 1]);
            if (p3)
#pragma unroll
                for (int a = 0; a < 2; a++)
#pragma unroll
                    for (int j = 0; j < 4; j++)
                        mma_bf16(acc2[a][j], al[a], &bh[j >> 1][(j & 1) << 1]);
        }
    }

    float rsum[2][4][4];
#pragma unroll
    for (int a = 0; a < 2; a++)
#pragma unroll
        for (int j = 0; j < 4; j++)
#pragma unroll
            for (int e = 0; e < 4; e++)
                rsum[a][j][e] = accm[a][j][e] + acc1[a][j][e] + acc2[a][j][e];

    __syncthreads();
    float* red = reinterpret_cast<float*>(smem + S_DATA);
    if (wk == 1) {
        float* dst = red + (wq << 10);
#pragma unroll
        for (int a = 0; a < 2; a++)
#pragma unroll
            for (int j = 0; j < 4; j++)
#pragma unroll
                for (int e = 0; e < 4; e++)
                    dst[((a << 4) | (j << 2) | e) << 5 | lane] = rsum[a][j][e];
    }
    __syncthreads();
    if (wk == 0) {
        const float* src = red + (wq << 10);
#pragma unroll
        for (int a = 0; a < 2; a++)
#pragma unroll
            for (int j = 0; j < 4; j++)
#pragma unroll
                for (int e = 0; e < 4; e++)
                    rsum[a][j][e] += src[((a << 4) | (j << 2) | e) << 5 | lane];

        float dmax = 0.0f;
        const int g  = lane >> 2;
        const int i2 = (lane & 3) << 1;
#pragma unroll
        for (int a = 0; a < 2; a++)
#pragma unroll
            for (int j = 0; j < 4; j++)
#pragma unroll
                for (int eh = 0; eh < 2; eh++) {
                    const int m = m0 + wm + (a << 4) + g + (eh << 3);
                    const int n = n0 + (j << 3) + i2;
                    const size_t idx = (size_t)m * D_H + n;
                    const float r0 = rsum[a][j][eh * 2 + 0];
                    const float r1 = rsum[a][j][eh * 2 + 1];
                    const float2 So = *reinterpret_cast<const float2*>(Sacc + idx);
                    const float Sn0 = So.x + r0, Sn1 = So.y + r1;
                    *reinterpret_cast<float2*>(Sacc + idx) = make_float2(Sn0, Sn1);
                    const float2 xb = *reinterpret_cast<const float2*>(xpb + idx);
                    const float2 ho = *reinterpret_cast<const float2*>(hold + idx);
                    const float hn0 = 0.5f * ho.x + 0.5f * tanhf(xb.x + Sn0);
                    const float hn1 = 0.5f * ho.y + 0.5f * tanhf(xb.y + Sn1);
                    *reinterpret_cast<float2*>(outF + idx) = make_float2(hn0, hn1);
                    const float2 h3v = *reinterpret_cast<const float2*>(h3 + idx);
                    const float d0 = hn0 - h3v.x, d1 = hn1 - h3v.y;
                    dmax = fmaxf(dmax, fmaxf(fabsf(d0), fabsf(d1)));
                    const __nv_bfloat16 dh0 = __float2bfloat16(d0);
                    const __nv_bfloat16 dh1 = __float2bfloat16(d1);
                    __nv_bfloat162 hv, lv;
                    hv.x = dh0; hv.y = dh1;
                    lv.x = __float2bfloat16(d0 - __bfloat162float(dh0));
                    lv.y = __float2bfloat16(d1 - __bfloat162float(dh1));
                    const size_t pidx = pkoff(m, n);
                    *reinterpret_cast<__nv_bfloat162*>(dNxtH + pidx) = hv;
                    *reinterpret_cast<__nv_bfloat162*>(dNxtL + pidx) = lv;
                    if (lidx == NLAUNCH - 1) {   // final h limbs for head GEMM
                        const __nv_bfloat16 b0 = __float2bfloat16(hn0);
                        const __nv_bfloat16 b1 = __float2bfloat16(hn1);
                        __nv_bfloat162 hh, hl;
                        hh.x = b0; hh.y = b1;
                        hl.x = __float2bfloat16(hn0 - __bfloat162float(b0));
                        hl.y = __float2bfloat16(hn1 - __bfloat162float(b1));
                        *reinterpret_cast<__nv_bfloat162*>(hPh + pidx) = hh;
                        *reinterpret_cast<__nv_bfloat162*>(hPl + pidx) = hl;
                    }
                }
#pragma unroll
        for (int o = 16; o > 0; o >>= 1)
            dmax = fmaxf(dmax, __shfl_xor_sync(0xffffffffu, dmax, o));
        if (lane == 0)
            atomicMax(reinterpret_cast<int*>(&maxd[lidx + 1]), __float_as_int(dmax));
    }
}

// ---------------- host ----------------
extern "C" void kernel_launch(void* const* d_in, const int* in_sizes, int n_in,
                              void* d_out, int out_size) {
    const float* x     = (const float*)d_in[0];
    const float* Winw  = (const float*)d_in[1];
    const float* Winb  = (const float*)d_in[2];
    const float* u     = (const float*)d_in[3];
    const float* W0    = (const float*)d_in[4];
    const float* b0    = (const float*)d_in[5];
    const float* W1    = (const float*)d_in[6];
    const float* b1    = (const float*)d_in[7];
    const float* W2    = (const float*)d_in[8];
    const float* b2    = (const float*)d_in[9];
    const float* headw = (const float*)d_in[10];
    const float* headb = (const float*)d_in[11];
    float* out = (float*)d_out;

    float *t, *s, *scal, *xpb, *Sacc, *hr, *maxd;
    cudaGetSymbolAddress((void**)&t, g_t);
    cudaGetSymbolAddress((void**)&s, g_s);
    cudaGetSymbolAddress((void**)&scal, g_scal);
    cudaGetSymbolAddress((void**)&xpb, g_xpb);
    cudaGetSymbolAddress((void**)&Sacc, g_S);
    cudaGetSymbolAddress((void**)&hr, g_hring);
    cudaGetSymbolAddress((void**)&maxd, g_maxd);
    char *W0hp, *W0lp, *W1hp, *W1lp, *W2hp, *W2lp;
    char *dPhA, *dPlA, *dPhB, *dPlB, *hPh, *hPl;
    cudaGetSymbolAddress((void**)&W0hp, g_W0hp); cudaGetSymbolAddress((void**)&W0lp, g_W0lp);
    cudaGetSymbolAddress((void**)&W1hp, g_W1hp); cudaGetSymbolAddress((void**)&W1lp, g_W1lp);
    cudaGetSymbolAddress((void**)&W2hp, g_W2hp); cudaGetSymbolAddress((void**)&W2lp, g_W2lp);
    cudaGetSymbolAddress((void**)&dPhA, g_dPhA); cudaGetSymbolAddress((void**)&dPlA, g_dPlA);
    cudaGetSymbolAddress((void**)&dPhB, g_dPhB); cudaGetSymbolAddress((void**)&dPlB, g_dPlB);
    cudaGetSymbolAddress((void**)&hPh, g_hPh);   cudaGetSymbolAddress((void**)&hPl, g_hPl);
    __nv_bfloat16 *Winh, *Winl, *Hdh, *Hdl, *xh, *xl;
    cudaGetSymbolAddress((void**)&Winh, g_Winhi); cudaGetSymbolAddress((void**)&Winl, g_Winlo);
    cudaGetSymbolAddress((void**)&Hdh, g_Hdhi);   cudaGetSymbolAddress((void**)&Hdl, g_Hdlo);
    cudaGetSymbolAddress((void**)&xh, g_xhi);     cudaGetSymbolAddress((void**)&xl, g_xlo);

    cudaFuncSetAttribute(gemm_mma<0, 0>, cudaFuncAttributeMaxDynamicSharedMemorySize, SMEM_BYTES);
    cudaFuncSetAttribute(gemm_mma<2, 1>, cudaFuncAttributeMaxDynamicSharedMemorySize, SMEM_BYTES);
    cudaFuncSetAttribute(gemm_step, cudaFuncAttributeMaxDynamicSharedMemorySize, S_SMEM);

    prep_kernel<<<592, 256>>>(W0, W1, W2, Winw, headw, x, u);
    sigma_kernel<<<64, 256>>>(Winw, t, s, scal);
    {
        dim3 grid(D_H / 64, BATCH / 64);
        gemm_mma<0, 0><<<grid, 128, SMEM_BYTES>>>(xh, xl, Winh, Winl, Winb,
                                                  nullptr, scal + 1, D_IN, D_H, D_H,
                                                  b0, b1, b2, xpb);
    }

    const char* Whp[3] = {W0hp, W1hp, W2hp};
    const char* Wlp[3] = {W0lp, W1lp, W2lp};
    char* dH[2] = {dPhA, dPhB};
    char* dL[2] = {dPlA, dPlB};
    const size_t HN = (size_t)BATCH * D_H;
    dim3 gstep(D_H / 32, BATCH / 64);
    for (int sidx = 0; sidx < NLAUNCH; sidx++) {
        const int l = sidx % 3;
        gemm_step<<<gstep, 128, S_SMEM>>>(
            dH[sidx & 1], dL[sidx & 1], Whp[l], Wlp[l],
            xpb + (size_t)l * HN, Sacc + (size_t)l * HN,
            hr + (size_t)((sidx + 3) & 3) * HN,     // hold = out(s-1)
            hr + (size_t)((sidx + 1) & 3) * HN,     // h3   = out(s-3)
            hr + (size_t)(sidx & 3) * HN,           // outF = out(s)
            dH[(sidx + 1) & 1], dL[(sidx + 1) & 1],
            hPh, hPl, maxd, sidx);
    }
    {
        dim3 grid((D_OUT + 63) / 64, BATCH / 64);
        gemm_mma<2, 1><<<grid, 128, SMEM_BYTES>>>(hPh, hPl, Hdh, Hdl, headb,
                                                  out, nullptr, D_H, D_OUT, D_OUT,
                                                  nullptr, nullptr, nullptr, nullptr);
    }
}

// round 16
// speedup vs baseline: 1.1901x; 1.0101x over previous
#include <cuda_runtime.h>
#include <cuda_bf16.h>
#include <math.h>
#include <stdint.h>

#define D_IN   1024
#define D_H    2048
#define BATCH  256
#define D_OUT  1000
#define EPSV   1e-12f
#define STEPS  30
#define NLAUNCH (3 * STEPS)

// ---- bf16 aux GEMM smem geometry (x_proj / head, 128-thread kernel) ----
#define ROW_B      144
#define TILE_A_HI  0
#define TILE_A_LO  9216
#define TILE_B_HI  18432
#define TILE_B_LO  27648
#define STAGE_BYTES 36864
#define SMEM_BYTES  (2 * STAGE_BYTES)

// ---- step GEMM: CTA tile 64x32, BK=128 panels, 2 stages, 2 CTAs/SM ----
#define SROW     272
#define ATILE    17408                // 64 rows * 272
#define BTILE    8704                 // 32 rows * 272
#define S_AH     0
#define S_AL     17408
#define S_BH     34816
#define S_BL     43520
#define S_STAGE  52224
#define S_DATA   128
#define S_SMEM   (S_DATA + 2 * S_STAGE)   // 104576

#define NKCH     16
__host__ __device__ __forceinline__ size_t pkoff(int r, int k) {
    return ((size_t)((r >> 6) * NKCH + (k >> 7))) * ATILE +
           (size_t)(r & 63) * SROW + (size_t)((k & 127) << 1);
}
__host__ __device__ __forceinline__ size_t pkoffW(int r, int k) {
    return ((size_t)((r >> 5) * NKCH + (k >> 7))) * BTILE +
           (size_t)(r & 31) * SROW + (size_t)((k & 127) << 1);
}

// ---------------- device scratch ----------------
__device__ float g_t[D_IN];
__device__ float g_s[D_H];
__device__ float g_scal[4];              // [1] = 1/sigma
__device__ int   g_ticket;
__device__ float g_xpb[3][BATCH * D_H];  // xproj + bias_l
__device__ float g_S[3][BATCH * D_H];    // running W_l . h accumulators
__device__ float g_hring[4][BATCH * D_H];// h output ring
__device__ float g_maxd[NLAUNCH + 2];    // per-launch max |delta|

#define WPK_BYTES ((size_t)64 * NKCH * BTILE)
#define HPK_BYTES ((size_t)4  * NKCH * ATILE)
__device__ char g_W0hp[WPK_BYTES], g_W0lp[WPK_BYTES];
__device__ char g_W1hp[WPK_BYTES], g_W1lp[WPK_BYTES];
__device__ char g_W2hp[WPK_BYTES], g_W2lp[WPK_BYTES];
__device__ char g_dPhA[HPK_BYTES], g_dPlA[HPK_BYTES];   // delta limb ping-pong
__device__ char g_dPhB[HPK_BYTES], g_dPlB[HPK_BYTES];
__device__ char g_hPh[HPK_BYTES], g_hPl[HPK_BYTES];     // final h limbs (head)

__device__ __nv_bfloat16 g_Winhi[D_H * D_IN], g_Winlo[D_H * D_IN];
__device__ __nv_bfloat16 g_Hdhi[D_OUT * D_H], g_Hdlo[D_OUT * D_H];
__device__ __nv_bfloat16 g_xhi[BATCH * D_IN], g_xlo[BATCH * D_IN];

// ---------------- portable PTX helpers ----------------
__device__ __forceinline__ uint32_t smem_u32(const void* p) {
    uint32_t a;
    asm("{ .reg .u64 t; cvta.to.shared.u64 t, %1; cvt.u32.u64 %0, t; }" : "=r"(a) : "l"(p));
    return a;
}
#define CP16(dst, src) asm volatile("cp.async.cg.shared.global [%0], [%1], 16;" :: "r"(dst), "l"(src))
#define CP_COMMIT()    asm volatile("cp.async.commit_group;" ::: "memory")
#define CP_WAIT(n)     asm volatile("cp.async.wait_group %0;" :: "n"(n) : "memory")

#define MBAR_INIT(a, c) asm volatile("mbarrier.init.shared.b64 [%0], %1;" :: "r"(a), "r"(c) : "memory")
#define MBAR_EXPECT(a, bytes) \
    asm volatile("mbarrier.arrive.expect_tx.shared.b64 _, [%0], %1;" :: "r"(a), "r"(bytes) : "memory")
// plain bulk (delta / state)
#define BULKA(dst, src, mbar) \
    asm volatile("cp.async.bulk.shared::cluster.global.mbarrier::complete_tx::bytes [%0], [%1], 17408, [%2];" \
        :: "r"(dst), "l"(src), "r"(mbar) : "memory")
// weight bulk with L2 evict_last cache hint (pin weights in L2)
#define BULKB_W(dst, src, mbar, pol) \
    asm volatile("cp.async.bulk.shared::cluster.global.mbarrier::complete_tx::bytes.L2::cache_hint [%0], [%1], 8704, [%2], %3;" \
        :: "r"(dst), "l"(src), "r"(mbar), "l"(pol) : "memory")
#define MBAR_WAIT(mbar, parity) do {                                              \
    uint32_t _m = (mbar), _p = (parity), _d;                                      \
    asm volatile("{ .reg .pred p; mbarrier.try_wait.parity.acquire.cta.shared::cta.b64 p, [%1], %2; selp.b32 %0, 1, 0, p; }" \
        : "=r"(_d) : "r"(_m), "r"(_p) : "memory");                                \
    if (!_d) {                                                                    \
        asm volatile("{ .reg .pred P1; WL_%=: mbarrier.try_wait.parity.acquire.cta.shared::cta.b64 P1, [%0], %1, 0x989680; @P1 bra.uni WD_%=; bra.uni WL_%=; WD_%=: }" \
            :: "r"(_m), "r"(_p) : "memory");                                      \
    }                                                                             \
} while (0)

__device__ __forceinline__ uint64_t mkpolicy_last() {
    uint64_t p;
    asm("createpolicy.fractional.L2::evict_last.b64 %0, 1.0;" : "=l"(p));
    return p;
}

__device__ __forceinline__ void ldsm4(uint32_t* r, uint32_t addr) {
    asm volatile("ldmatrix.sync.aligned.m8n8.x4.shared.b16 {%0,%1,%2,%3}, [%4];"
        : "=r"(r[0]), "=r"(r[1]), "=r"(r[2]), "=r"(r[3]) : "r"(addr));
}
__device__ __forceinline__ void mma_bf16(float* c, const uint32_t* a, const uint32_t* b) {
    asm volatile("mma.sync.aligned.m16n8k16.row.col.f32.bf16.bf16.f32 "
        "{%0,%1,%2,%3}, {%4,%5,%6,%7}, {%8,%9}, {%0,%1,%2,%3};"
        : "+f"(c[0]), "+f"(c[1]), "+f"(c[2]), "+f"(c[3])
        : "r"(a[0]), "r"(a[1]), "r"(a[2]), "r"(a[3]), "r"(b[0]), "r"(b[1]));
}

// ---------------- prep ----------------
__device__ __forceinline__ void split_plain(const float* __restrict__ src,
        __nv_bfloat16* __restrict__ hi, __nv_bfloat16* __restrict__ lo, int i) {
    float a = src[i];
    __nv_bfloat16 h = __float2bfloat16(a);
    hi[i] = h;
    lo[i] = __float2bfloat16(a - __bfloat162float(h));
}
__device__ __forceinline__ void split_packW(const float* __restrict__ src,
        char* __restrict__ hp, char* __restrict__ lp, int i) {
    const int r = i >> 11, k = i & 2047;
    const size_t off = pkoffW(r, k);
    float a = src[i];
    __nv_bfloat16 h = __float2bfloat16(a);
    *reinterpret_cast<__nv_bfloat16*>(hp + off) = h;
    *reinterpret_cast<__nv_bfloat16*>(lp + off) =
        __float2bfloat16(a - __bfloat162float(h));
}

__global__ void prep_kernel(const float* __restrict__ W0, const float* __restrict__ W1,
                            const float* __restrict__ W2, const float* __restrict__ Win,
                            const float* __restrict__ Hd, const float* __restrict__ x,
                            const float* __restrict__ u) {
    const int stride = gridDim.x * blockDim.x;
    const int t0 = blockIdx.x * blockDim.x + threadIdx.x;
    if (t0 == 0) g_ticket = 0;
    for (int i = t0; i < NLAUNCH + 2; i += stride) g_maxd[i] = 0.0f;
    for (int i = t0; i < D_H * D_H; i += stride) {
        split_packW(W0, g_W0hp, g_W0lp, i);
        split_packW(W1, g_W1hp, g_W1lp, i);
        split_packW(W2, g_W2hp, g_W2lp, i);
    }
    for (int i = t0; i < D_H * D_IN; i += stride) split_plain(Win, g_Winhi, g_Winlo, i);
    for (int i = t0; i < D_OUT * D_H; i += stride) split_plain(Hd, g_Hdhi, g_Hdlo, i);
    for (int i = t0; i < BATCH * D_IN; i += stride) split_plain(x, g_xhi, g_xlo, i);
    for (int i = t0; i < BATCH * D_H; i += stride) {
        g_S[0][i] = 0.0f; g_S[1][i] = 0.0f; g_S[2][i] = 0.0f;
        g_hring[0][i] = 0.0f; g_hring[1][i] = 0.0f;
        g_hring[2][i] = 0.0f; g_hring[3][i] = 0.0f;
    }
    for (int i = t0; i < (int)(HPK_BYTES / 4); i += stride) {
        reinterpret_cast<uint32_t*>(g_dPhA)[i] = 0u;
        reinterpret_cast<uint32_t*>(g_dPlA)[i] = 0u;
    }
    for (int j = t0; j < D_IN; j += stride) {
        float acc = 0.0f;
#pragma unroll 4
        for (int i = 0; i < D_H; i++) acc = fmaf(Win[(size_t)i * D_IN + j], u[i], acc);
        g_t[j] = acc;
    }
}

// ---------------- sigma ----------------
__global__ void sigma_kernel(const float* __restrict__ W, const float* __restrict__ t,
                             float* __restrict__ s, float* __restrict__ scal) {
    __shared__ float shw[8];
    __shared__ int lastf;
    const int tid = threadIdx.x;
    const int lane = tid & 31;
    const int w = tid >> 5;
    float ss = 0.0f;
#pragma unroll
    for (int i = 0; i < 4; i++) {
        float v = t[tid + (i << 8)];
        ss = fmaf(v, v, ss);
    }
#pragma unroll
    for (int o = 16; o > 0; o >>= 1) ss += __shfl_xor_sync(0xffffffffu, ss, o);
    if (lane == 0) shw[w] = ss;
    __syncthreads();
    float tot = shw[lane & 7];
#pragma unroll
    for (int o = 4; o > 0; o >>= 1) tot += __shfl_xor_sync(0xffffffffu, tot, o);
    const float invn = 1.0f / (sqrtf(tot) + EPSV);

    const int gwarp = blockIdx.x * 8 + w;
    for (int r = gwarp; r < D_H; r += 512) {
        const float* row = W + (size_t)r * D_IN;
        float acc = 0.0f;
        for (int j = lane; j < D_IN; j += 32) acc = fmaf(row[j], t[j], acc);
#pragma unroll
        for (int o = 16; o > 0; o >>= 1) acc += __shfl_xor_sync(0xffffffffu, acc, o);
        if (lane == 0) s[r] = acc * invn;
    }
    __threadfence();
    if (tid == 0) lastf = (atomicAdd(&g_ticket, 1) == (int)gridDim.x - 1);
    __syncthreads();
    if (lastf) {
        __threadfence();
        float q = 0.0f;
        for (int i = tid; i < D_H; i += 256) { float v = s[i]; q = fmaf(v, v, q); }
#pragma unroll
        for (int o = 16; o > 0; o >>= 1) q += __shfl_xor_sync(0xffffffffu, q, o);
        if (lane == 0) shw[w] = q;
        __syncthreads();
        if (tid == 0) {
            float Q = 0.0f;
#pragma unroll
            for (int i = 0; i < 8; i++) Q += shw[i];
            scal[1] = (sqrtf(Q) + EPSV) / Q;
        }
    }
}

// ================= bf16 3-pass aux GEMM (x_proj MODE 0, head MODE 2) =================
template <int AP>
__device__ __forceinline__ void prefetch_chunk(uint32_t sb_u, char* sb_p, int k0,
        const void* Ahi, const void* Alo,
        const __nv_bfloat16* __restrict__ Bhi, const __nv_bfloat16* __restrict__ Blo,
        int K, int NB, int m0, int n0) {
    const int t = threadIdx.x;
#pragma unroll
    for (int r = 0; r < 4; r++) {
        const int idx = t + (r << 7);
        const int row = idx >> 3;
        const int c   = idx & 7;
        const uint32_t soff = (uint32_t)row * ROW_B + (c << 4);
        const void *pa, *pl;
        if (AP == 0) {
            const size_t ga = (size_t)(m0 + row) * K + k0 + (c << 3);
            pa = (const __nv_bfloat16*)Ahi + ga;
            pl = (const __nv_bfloat16*)Alo + ga;
        } else {
            const size_t gb = ((size_t)((m0 >> 6) * NKCH + (k0 >> 7))) * ATILE +
                              (size_t)row * SROW + ((k0 & 127) << 1) + (c << 4);
            pa = (const char*)Ahi + gb;
            pl = (const char*)Alo + gb;
        }
        CP16(sb_u + TILE_A_HI + soff, pa);
        CP16(sb_u + TILE_A_LO + soff, pl);
        const int gn = n0 + row;
        if (gn < NB) {
            const size_t gb2 = (size_t)gn * K + k0 + (c << 3);
            CP16(sb_u + TILE_B_HI + soff, Bhi + gb2);
            CP16(sb_u + TILE_B_LO + soff, Blo + gb2);
        } else {
            const uint4 z = make_uint4(0, 0, 0, 0);
            *reinterpret_cast<uint4*>(sb_p + TILE_B_HI + soff) = z;
            *reinterpret_cast<uint4*>(sb_p + TILE_B_LO + soff) = z;
        }
    }
}

template <int MODE, int AP>
__global__ void __launch_bounds__(128)
gemm_mma(const void* Ahi, const void* Alo,
         const __nv_bfloat16* __restrict__ Bhi, const __nv_bfloat16* __restrict__ Blo,
         const float* __restrict__ bias, float* __restrict__ outF,
         const float* __restrict__ scale_ptr, int K, int NB, int ldOut,
         const float* __restrict__ lb0, const float* __restrict__ lb1,
         const float* __restrict__ lb2, float* __restrict__ xpb) {
    extern __shared__ char smem[];
    const uint32_t sbase = smem_u32(smem);
    const int tid  = threadIdx.x;
    const int lane = tid & 31;
    const int wid  = tid >> 5;
    const int m0 = blockIdx.y * 64;
    const int n0 = blockIdx.x * 64;
    const int wm = (wid >> 1) << 5;
    const int wn = (wid & 1) << 5;
    const int NC = K >> 6;

    const int arow  = (lane & 7) | (((lane >> 3) & 1) << 3);
    const int akoff = ((lane >> 4) & 1) << 3;
    const int brow  = (lane & 7) | (((lane >> 4) & 1) << 3);
    const int bkoff = ((lane >> 3) & 1) << 3;

    float acc[2][4][4] = {};

    prefetch_chunk<AP>(sbase, smem, 0, Ahi, Alo, Bhi, Blo, K, NB, m0, n0);
    CP_COMMIT();

    for (int c = 0; c < NC; c++) {
        if (c + 1 < NC) {
            const int ns = (c + 1) & 1;
            prefetch_chunk<AP>(sbase + ns * STAGE_BYTES, smem + ns * STAGE_BYTES,
                               (c + 1) << 6, Ahi, Alo, Bhi, Blo, K, NB, m0, n0);
            CP_COMMIT();
            CP_WAIT(1);
        } else {
            CP_WAIT(0);
        }
        __syncthreads();

        const uint32_t st = sbase + (c & 1) * STAGE_BYTES;
#pragma unroll
        for (int kk = 0; kk < 4; kk++) {
            const int k0 = kk << 4;
            uint32_t ah[2][4], al[2][4], bh[2][4], bl[2][4];
#pragma unroll
            for (int a = 0; a < 2; a++) {
                const uint32_t off = (uint32_t)(wm + (a << 4) + arow) * ROW_B +
                                     ((k0 + akoff) << 1);
                ldsm4(ah[a], st + TILE_A_HI + off);
                ldsm4(al[a], st + TILE_A_LO + off);
            }
#pragma unroll
            for (int b = 0; b < 2; b++) {
                const uint32_t off = (uint32_t)(wn + (b << 4) + brow) * ROW_B +
                                     ((k0 + bkoff) << 1);
                ldsm4(bh[b], st + TILE_B_HI + off);
                ldsm4(bl[b], st + TILE_B_LO + off);
            }
#pragma unroll
            for (int a = 0; a < 2; a++)
#pragma unroll
                for (int j = 0; j < 4; j++)
                    mma_bf16(acc[a][j], ah[a], &bh[j >> 1][(j & 1) << 1]);
#pragma unroll
            for (int a = 0; a < 2; a++)
#pragma unroll
                for (int j = 0; j < 4; j++)
                    mma_bf16(acc[a][j], ah[a], &bl[j >> 1][(j & 1) << 1]);
#pragma unroll
            for (int a = 0; a < 2; a++)
#pragma unroll
                for (int j = 0; j < 4; j++)
                    mma_bf16(acc[a][j], al[a], &bh[j >> 1][(j & 1) << 1]);
        }
        __syncthreads();
    }

    const float scale = (MODE == 0) ? *scale_ptr : 1.0f;
    const int g  = lane >> 2;
    const int i2 = (lane & 3) << 1;
#pragma unroll
    for (int a = 0; a < 2; a++)
#pragma unroll
        for (int j = 0; j < 4; j++)
#pragma unroll
            for (int e = 0; e < 4; e++) {
                const int m = m0 + wm + (a << 4) + g + ((e >> 1) << 3);
                const int n = n0 + wn + (j << 3) + i2 + (e & 1);
                const float r = acc[a][j][e];
                if (MODE == 0) {
                    const float v = fmaf(r, scale, bias[n]);
                    const size_t idx = (size_t)m * D_H + n;
                    xpb[idx] = v + lb0[n];
                    xpb[(size_t)BATCH * D_H + idx] = v + lb1[n];
                    xpb[(size_t)2 * BATCH * D_H + idx] = v + lb2[n];
                } else {
                    if (n < NB) outF[(size_t)m * ldOut + n] = r + bias[n];
                }
            }
}

// ====== step GEMM: delta-form, adaptive pass count, weights pinned in L2 ======
__global__ void __launch_bounds__(128)
gemm_step(const char* __restrict__ dAH, const char* __restrict__ dAL,
          const char* __restrict__ WH, const char* __restrict__ WL,
          const float* __restrict__ xpb, float* __restrict__ Sacc,
          const float* __restrict__ hold, const float* __restrict__ h3,
          float* __restrict__ outF,
          char* __restrict__ dNxtH, char* __restrict__ dNxtL,
          char* __restrict__ hPh, char* __restrict__ hPl,
          float* __restrict__ maxd, int lidx) {
    extern __shared__ char smem[];
    const uint32_t sbase = smem_u32(smem);
    const uint32_t data0 = sbase + S_DATA;
    const int tid  = threadIdx.x;
    const int lane = tid & 31;
    const int wid  = tid >> 5;
    const int wk   = wid & 1;
    const int wq   = wid >> 1;
    const int nt = blockIdx.x;
    const int mt = blockIdx.y;
    const int m0 = mt << 6;
    const int n0 = nt << 5;
    const int wm = wq << 5;
    const int NC = NKCH;

    // adaptive pass count from previous launch's max |delta|
    const float md = __ldg(&maxd[lidx]);
    const int p3 = (md >= 2e-2f);
    const int p2 = (md >= 2e-3f);
    const uint32_t tx = 17408u + 8704u + (p2 ? 8704u : 0u) + (p3 ? 17408u : 0u);
    const uint64_t polW = mkpolicy_last();

    const int arow  = (lane & 7) | (((lane >> 3) & 1) << 3);
    const int akoff = ((lane >> 4) & 1) << 3;
    const int brow  = (lane & 7) | (((lane >> 4) & 1) << 3);
    const int bkoff = ((lane >> 3) & 1) << 3;
    const int kbase = wk << 2;

    float accm[2][4][4] = {};
    float acc1[2][4][4] = {};
    float acc2[2][4][4] = {};

    if (tid == 0) { MBAR_INIT(sbase + 0, 1); MBAR_INIT(sbase + 16, 1); }
    __syncthreads();
    if (tid == 0) {
        MBAR_EXPECT(sbase + 0, tx);
        const size_t ab = ((size_t)(mt * NKCH)) * ATILE;
        const size_t bb = ((size_t)(nt * NKCH)) * BTILE;
        BULKA(data0 + S_AH, dAH + ab, sbase + 0);
        if (p3) BULKA(data0 + S_AL, dAL + ab, sbase + 0);
        BULKB_W(data0 + S_BH, WH + bb, sbase + 0, polW);
        if (p2) BULKB_W(data0 + S_BL, WL + bb, sbase + 0, polW);
    }

    for (int c = 0; c < NC; c++) {
        const int s = c & 1;
        if (c + 1 < NC) {
            __syncthreads();
            if (tid == 0) {
                const uint32_t mb = sbase + ((s ^ 1) << 4);
                const uint32_t dst = data0 + (s ^ 1) * S_STAGE;
                MBAR_EXPECT(mb, tx);
                const size_t ab = ((size_t)(mt * NKCH + c + 1)) * ATILE;
                const size_t bb = ((size_t)(nt * NKCH + c + 1)) * BTILE;
                BULKA(dst + S_AH, dAH + ab, mb);
                if (p3) BULKA(dst + S_AL, dAL + ab, mb);
                BULKB_W(dst + S_BH, WH + bb, mb, polW);
                if (p2) BULKB_W(dst + S_BL, WL + bb, mb, polW);
            }
        }
        MBAR_WAIT(sbase + (s << 4), (c >> 1) & 1);

        const uint32_t st = data0 + s * S_STAGE;
#pragma unroll
        for (int kki = 0; kki < 4; kki++) {
            const int k0 = (kbase + kki) << 4;
            uint32_t ah[2][4], al[2][4], bh[2][4], bl[2][4];
#pragma unroll
            for (int a = 0; a < 2; a++) {
                const uint32_t off = (uint32_t)(wm + (a << 4) + arow) * SROW +
                                     ((k0 + akoff) << 1);
                ldsm4(ah[a], st + S_AH + off);
            }
            if (p3)
#pragma unroll
                for (int a = 0; a < 2; a++) {
                    const uint32_t off = (uint32_t)(wm + (a << 4) + arow) * SROW +
                                         ((k0 + akoff) << 1);
                    ldsm4(al[a], st + S_AL + off);
                }
#pragma unroll
            for (int b = 0; b < 2; b++) {
                const uint32_t off = (uint32_t)((b << 4) + brow) * SROW +
                                     ((k0 + bkoff) << 1);
                ldsm4(bh[b], st + S_BH + off);
            }
            if (p2)
#pragma unroll
                for (int b = 0; b < 2; b++) {
                    const uint32_t off = (uint32_t)((b << 4) + brow) * SROW +
                                         ((k0 + bkoff) << 1);
                    ldsm4(bl[b], st + S_BL + off);
                }
#pragma unroll
            for (int a = 0; a < 2; a++)
#pragma unroll
                for (int j = 0; j < 4; j++)
                    mma_bf16(accm[a][j], ah[a], &bh[j >> 1][(j & 1) << 1]);
            if (p2)
#pragma unroll
                for (int a = 0; a < 2; a++)
#pragma unroll
                    for (int j = 0; j < 4; j++)
                        mma_bf16(acc1[a][j], ah[a], &bl[j >> 1][(j & 1) << 1]);
            if (p3)
#pragma unroll
                for (int a = 0; a < 2; a++)
#pragma unroll
                    for (int j = 0; j < 4; j++)
                        mma_bf16(acc2[a][j], al[a], &bh[j >> 1][(j & 1) << 1]);
        }
    }

    float rsum[2][4][4];
#pragma unroll
    for (int a = 0; a < 2; a++)
#pragma unroll
        for (int j = 0; j < 4; j++)
#pragma unroll
            for (int e = 0; e < 4; e++)
                rsum[a][j][e] = accm[a][j][e] + acc1[a][j][e] + acc2[a][j][e];

    __syncthreads();
    float* red = reinterpret_cast<float*>(smem + S_DATA);
    if (wk == 1) {
        float* dst = red + (wq << 10);
#pragma unroll
        for (int a = 0; a < 2; a++)
#pragma unroll
            for (int j = 0; j < 4; j++)
#pragma unroll
                for (int e = 0; e < 4; e++)
                    dst[((a << 4) | (j << 2) | e) << 5 | lane] = rsum[a][j][e];
    }
    __syncthreads();
    if (wk == 0) {
        const float* src = red + (wq << 10);
#pragma unroll
        for (int a = 0; a < 2; a++)
#pragma unroll
            for (int j = 0; j < 4; j++)
#pragma unroll
                for (int e = 0; e < 4; e++)
                    rsum[a][j][e] += src[((a << 4) | (j << 2) | e) << 5 | lane];

        float dmax = 0.0f;
        const int g  = lane >> 2;
        const int i2 = (lane & 3) << 1;
#pragma unroll
        for (int a = 0; a < 2; a++)
#pragma unroll
            for (int j = 0; j < 4; j++)
#pragma unroll
                for (int eh = 0; eh < 2; eh++) {
                    const int m = m0 + wm + (a << 4) + g + (eh << 3);
                    const int n = n0 + (j << 3) + i2;
                    const size_t idx = (size_t)m * D_H + n;
                    const float r0 = rsum[a][j][eh * 2 + 0];
                    const float r1 = rsum[a][j][eh * 2 + 1];
                    const float2 So = *reinterpret_cast<const float2*>(Sacc + idx);
                    const float Sn0 = So.x + r0, Sn1 = So.y + r1;
                    *reinterpret_cast<float2*>(Sacc + idx) = make_float2(Sn0, Sn1);
                    const float2 xb = *reinterpret_cast<const float2*>(xpb + idx);
                    const float2 ho = *reinterpret_cast<const float2*>(hold + idx);
                    const float hn0 = 0.5f * ho.x + 0.5f * tanhf(xb.x + Sn0);
                    const float hn1 = 0.5f * ho.y + 0.5f * tanhf(xb.y + Sn1);
                    *reinterpret_cast<float2*>(outF + idx) = make_float2(hn0, hn1);
                    const float2 h3v = *reinterpret_cast<const float2*>(h3 + idx);
                    const float d0 = hn0 - h3v.x, d1 = hn1 - h3v.y;
                    dmax = fmaxf(dmax, fmaxf(fabsf(d0), fabsf(d1)));
                    const __nv_bfloat16 dh0 = __float2bfloat16(d0);
                    const __nv_bfloat16 dh1 = __float2bfloat16(d1);
                    __nv_bfloat162 hv, lv;
                    hv.x = dh0; hv.y = dh1;
                    lv.x = __float2bfloat16(d0 - __bfloat162float(dh0));
                    lv.y = __float2bfloat16(d1 - __bfloat162float(dh1));
                    const size_t pidx = pkoff(m, n);
                    *reinterpret_cast<__nv_bfloat162*>(dNxtH + pidx) = hv;
                    *reinterpret_cast<__nv_bfloat162*>(dNxtL + pidx) = lv;
                    if (lidx == NLAUNCH - 1) {   // final h limbs for head GEMM
                        const __nv_bfloat16 b0 = __float2bfloat16(hn0);
                        const __nv_bfloat16 b1 = __float2bfloat16(hn1);
                        __nv_bfloat162 hh, hl;
                        hh.x = b0; hh.y = b1;
                        hl.x = __float2bfloat16(hn0 - __bfloat162float(b0));
                        hl.y = __float2bfloat16(hn1 - __bfloat162float(b1));
                        *reinterpret_cast<__nv_bfloat162*>(hPh + pidx) = hh;
                        *reinterpret_cast<__nv_bfloat162*>(hPl + pidx) = hl;
                    }
                }
#pragma unroll
        for (int o = 16; o > 0; o >>= 1)
            dmax = fmaxf(dmax, __shfl_xor_sync(0xffffffffu, dmax, o));
        if (lane == 0)
            atomicMax(reinterpret_cast<int*>(&maxd[lidx + 1]), __float_as_int(dmax));
    }
}

// ---------------- host ----------------
extern "C" void kernel_launch(void* const* d_in, const int* in_sizes, int n_in,
                              void* d_out, int out_size) {
    const float* x     = (const float*)d_in[0];
    const float* Winw  = (const float*)d_in[1];
    const float* Winb  = (const float*)d_in[2];
    const float* u     = (const float*)d_in[3];
    const float* W0    = (const float*)d_in[4];
    const float* b0    = (const float*)d_in[5];
    const float* W1    = (const float*)d_in[6];
    const float* b1    = (const float*)d_in[7];
    const float* W2    = (const float*)d_in[8];
    const float* b2    = (const float*)d_in[9];
    const float* headw = (const float*)d_in[10];
    const float* headb = (const float*)d_in[11];
    float* out = (float*)d_out;

    float *t, *s, *scal, *xpb, *Sacc, *hr, *maxd;
    cudaGetSymbolAddress((void**)&t, g_t);
    cudaGetSymbolAddress((void**)&s, g_s);
    cudaGetSymbolAddress((void**)&scal, g_scal);
    cudaGetSymbolAddress((void**)&xpb, g_xpb);
    cudaGetSymbolAddress((void**)&Sacc, g_S);
    cudaGetSymbolAddress((void**)&hr, g_hring);
    cudaGetSymbolAddress((void**)&maxd, g_maxd);
    char *W0hp, *W0lp, *W1hp, *W1lp, *W2hp, *W2lp;
    char *dPhA, *dPlA, *dPhB, *dPlB, *hPh, *hPl;
    cudaGetSymbolAddress((void**)&W0hp, g_W0hp); cudaGetSymbolAddress((void**)&W0lp, g_W0lp);
    cudaGetSymbolAddress((void**)&W1hp, g_W1hp); cudaGetSymbolAddress((void**)&W1lp, g_W1lp);
    cudaGetSymbolAddress((void**)&W2hp, g_W2hp); cudaGetSymbolAddress((void**)&W2lp, g_W2lp);
    cudaGetSymbolAddress((void**)&dPhA, g_dPhA); cudaGetSymbolAddress((void**)&dPlA, g_dPlA);
    cudaGetSymbolAddress((void**)&dPhB, g_dPhB); cudaGetSymbolAddress((void**)&dPlB, g_dPlB);
    cudaGetSymbolAddress((void**)&hPh, g_hPh);   cudaGetSymbolAddress((void**)&hPl, g_hPl);
    __nv_bfloat16 *Winh, *Winl, *Hdh, *Hdl, *xh, *xl;
    cudaGetSymbolAddress((void**)&Winh, g_Winhi); cudaGetSymbolAddress((void**)&Winl, g_Winlo);
    cudaGetSymbolAddress((void**)&Hdh, g_Hdhi);   cudaGetSymbolAddress((void**)&Hdl, g_Hdlo);
    cudaGetSymbolAddress((void**)&xh, g_xhi);     cudaGetSymbolAddress((void**)&xl, g_xlo);

    cudaFuncSetAttribute(gemm_mma<0, 0>, cudaFuncAttributeMaxDynamicSharedMemorySize, SMEM_BYTES);
    cudaFuncSetAttribute(gemm_mma<2, 1>, cudaFuncAttributeMaxDynamicSharedMemorySize, SMEM_BYTES);
    cudaFuncSetAttribute(gemm_step, cudaFuncAttributeMaxDynamicSharedMemorySize, S_SMEM);

    prep_kernel<<<592, 256>>>(W0, W1, W2, Winw, headw, x, u);
    sigma_kernel<<<64, 256>>>(Winw, t, s, scal);
    {
        dim3 grid(D_H / 64, BATCH / 64);
        gemm_mma<0, 0><<<grid, 128, SMEM_BYTES>>>(xh, xl, Winh, Winl, Winb,
                                                  nullptr, scal + 1, D_IN, D_H, D_H,
                                                  b0, b1, b2, xpb);
    }

    const char* Whp[3] = {W0hp, W1hp, W2hp};
    const char* Wlp[3] = {W0lp, W1lp, W2lp};
    char* dH[2] = {dPhA, dPhB};
    char* dL[2] = {dPlA, dPlB};
    const size_t HN = (size_t)BATCH * D_H;
    dim3 gstep(D_H / 32, BATCH / 64);
    for (int sidx = 0; sidx < NLAUNCH; sidx++) {
        const int l = sidx % 3;
        gemm_step<<<gstep, 128, S_SMEM>>>(
            dH[sidx & 1], dL[sidx & 1], Whp[l], Wlp[l],
            xpb + (size_t)l * HN, Sacc + (size_t)l * HN,
            hr + (size_t)((sidx + 3) & 3) * HN,     // hold = out(s-1)
            hr + (size_t)((sidx + 1) & 3) * HN,     // h3   = out(s-3)
            hr + (size_t)(sidx & 3) * HN,           // outF = out(s)
            dH[(sidx + 1) & 1], dL[(sidx + 1) & 1],
            hPh, hPl, maxd, sidx);
    }
    {
        dim3 grid((D_OUT + 63) / 64, BATCH / 64);
        gemm_mma<2, 1><<<grid, 128, SMEM_BYTES>>>(hPh, hPl, Hdh, Hdl, headb,
                                                  out, nullptr, D_H, D_OUT, D_OUT,
                                                  nullptr, nullptr, nullptr, nullptr);
    }
}

// round 17
// speedup vs baseline: 1.2182x; 1.0236x over previous
#include <cuda_runtime.h>
#include <cuda_bf16.h>
#include <math.h>
#include <stdint.h>

#define D_IN   1024
#define D_H    2048
#define BATCH  256
#define D_OUT  1000
#define EPSV   1e-12f
#define STEPS  30
#define NLAUNCH (3 * STEPS)

// ---- bf16 aux GEMM smem geometry (x_proj / head, 128-thread kernel) ----
#define ROW_B      144
#define TILE_A_HI  0
#define TILE_A_LO  9216
#define TILE_B_HI  18432
#define TILE_B_LO  27648
#define STAGE_BYTES 36864
#define SMEM_BYTES  (2 * STAGE_BYTES)

// ---- step GEMM: CTA tile 64x32, BK=128 panels, adaptive stages, 2 CTAs/SM ----
#define SROW     272
#define ATILE    17408                // 64 rows * 272
#define BTILE    8704                 // 32 rows * 272
// stage-internal offsets (order: AH, BH, [BL], [AL])
#define S2_AH    0
#define S2_BH    17408
#define S2_BL    26112
#define S2_AL    34816
#define S_DATA   128                  // 4 mbarriers below
#define S_POOL   104448               // stage pool bytes (4*26112 = 3*34816 = 2*52224)
#define S_SMEM   (S_DATA + S_POOL)    // 104576

#define NKCH     16
__host__ __device__ __forceinline__ size_t pkoff(int r, int k) {
    return ((size_t)((r >> 6) * NKCH + (k >> 7))) * ATILE +
           (size_t)(r & 63) * SROW + (size_t)((k & 127) << 1);
}
__host__ __device__ __forceinline__ size_t pkoffW(int r, int k) {
    return ((size_t)((r >> 5) * NKCH + (k >> 7))) * BTILE +
           (size_t)(r & 31) * SROW + (size_t)((k & 127) << 1);
}

// ---------------- device scratch ----------------
__device__ float g_t[D_IN];
__device__ float g_s[D_H];
__device__ float g_scal[4];              // [1] = 1/sigma
__device__ int   g_ticket;
__device__ float g_xpb[3][BATCH * D_H];  // xproj + bias_l
__device__ float g_S[3][BATCH * D_H];    // running W_l . h accumulators
__device__ float g_hring[4][BATCH * D_H];// h output ring
__device__ float g_maxd[NLAUNCH + 2];    // per-launch max |delta|

#define WPK_BYTES ((size_t)64 * NKCH * BTILE)
#define HPK_BYTES ((size_t)4  * NKCH * ATILE)
__device__ char g_W0hp[WPK_BYTES], g_W0lp[WPK_BYTES];
__device__ char g_W1hp[WPK_BYTES], g_W1lp[WPK_BYTES];
__device__ char g_W2hp[WPK_BYTES], g_W2lp[WPK_BYTES];
__device__ char g_dPhA[HPK_BYTES], g_dPlA[HPK_BYTES];   // delta limb ping-pong
__device__ char g_dPhB[HPK_BYTES], g_dPlB[HPK_BYTES];
__device__ char g_hPh[HPK_BYTES], g_hPl[HPK_BYTES];     // final h limbs (head)

__device__ __nv_bfloat16 g_Winhi[D_H * D_IN], g_Winlo[D_H * D_IN];
__device__ __nv_bfloat16 g_Hdhi[D_OUT * D_H], g_Hdlo[D_OUT * D_H];
__device__ __nv_bfloat16 g_xhi[BATCH * D_IN], g_xlo[BATCH * D_IN];

// ---------------- portable PTX helpers ----------------
__device__ __forceinline__ uint32_t smem_u32(const void* p) {
    uint32_t a;
    asm("{ .reg .u64 t; cvta.to.shared.u64 t, %1; cvt.u32.u64 %0, t; }" : "=r"(a) : "l"(p));
    return a;
}
#define CP16(dst, src) asm volatile("cp.async.cg.shared.global [%0], [%1], 16;" :: "r"(dst), "l"(src))
#define CP_COMMIT()    asm volatile("cp.async.commit_group;" ::: "memory")
#define CP_WAIT(n)     asm volatile("cp.async.wait_group %0;" :: "n"(n) : "memory")

#define MBAR_INIT(a, c) asm volatile("mbarrier.init.shared.b64 [%0], %1;" :: "r"(a), "r"(c) : "memory")
#define MBAR_EXPECT(a, bytes) \
    asm volatile("mbarrier.arrive.expect_tx.shared.b64 _, [%0], %1;" :: "r"(a), "r"(bytes) : "memory")
#define BULKA(dst, src, mbar) \
    asm volatile("cp.async.bulk.shared::cluster.global.mbarrier::complete_tx::bytes [%0], [%1], 17408, [%2];" \
        :: "r"(dst), "l"(src), "r"(mbar) : "memory")
#define BULKB_W(dst, src, mbar, pol) \
    asm volatile("cp.async.bulk.shared::cluster.global.mbarrier::complete_tx::bytes.L2::cache_hint [%0], [%1], 8704, [%2], %3;" \
        :: "r"(dst), "l"(src), "r"(mbar), "l"(pol) : "memory")
#define MBAR_WAIT(mbar, parity) do {                                              \
    uint32_t _m = (mbar), _p = (parity), _d;                                      \
    asm volatile("{ .reg .pred p; mbarrier.try_wait.parity.acquire.cta.shared::cta.b64 p, [%1], %2; selp.b32 %0, 1, 0, p; }" \
        : "=r"(_d) : "r"(_m), "r"(_p) : "memory");                                \
    if (!_d) {                                                                    \
        asm volatile("{ .reg .pred P1; WL_%=: mbarrier.try_wait.parity.acquire.cta.shared::cta.b64 P1, [%0], %1, 0x989680; @P1 bra.uni WD_%=; bra.uni WL_%=; WD_%=: }" \
            :: "r"(_m), "r"(_p) : "memory");                                      \
    }                                                                             \
} while (0)

__device__ __forceinline__ uint64_t mkpolicy_last() {
    uint64_t p;
    asm("createpolicy.fractional.L2::evict_last.b64 %0, 1.0;" : "=l"(p));
    return p;
}

__device__ __forceinline__ void ldsm4(uint32_t* r, uint32_t addr) {
    asm volatile("ldmatrix.sync.aligned.m8n8.x4.shared.b16 {%0,%1,%2,%3}, [%4];"
        : "=r"(r[0]), "=r"(r[1]), "=r"(r[2]), "=r"(r[3]) : "r"(addr));
}
__device__ __forceinline__ void mma_bf16(float* c, const uint32_t* a, const uint32_t* b) {
    asm volatile("mma.sync.aligned.m16n8k16.row.col.f32.bf16.bf16.f32 "
        "{%0,%1,%2,%3}, {%4,%5,%6,%7}, {%8,%9}, {%0,%1,%2,%3};"
        : "+f"(c[0]), "+f"(c[1]), "+f"(c[2]), "+f"(c[3])
        : "r"(a[0]), "r"(a[1]), "r"(a[2]), "r"(a[3]), "r"(b[0]), "r"(b[1]));
}

// ---------------- prep ----------------
__device__ __forceinline__ void split_plain(const float* __restrict__ src,
        __nv_bfloat16* __restrict__ hi, __nv_bfloat16* __restrict__ lo, int i) {
    float a = src[i];
    __nv_bfloat16 h = __float2bfloat16(a);
    hi[i] = h;
    lo[i] = __float2bfloat16(a - __bfloat162float(h));
}
__device__ __forceinline__ void split_packW(const float* __restrict__ src,
        char* __restrict__ hp, char* __restrict__ lp, int i) {
    const int r = i >> 11, k = i & 2047;
    const size_t off = pkoffW(r, k);
    float a = src[i];
    __nv_bfloat16 h = __float2bfloat16(a);
    *reinterpret_cast<__nv_bfloat16*>(hp + off) = h;
    *reinterpret_cast<__nv_bfloat16*>(lp + off) =
        __float2bfloat16(a - __bfloat162float(h));
}

__global__ void prep_kernel(const float* __restrict__ W0, const float* __restrict__ W1,
                            const float* __restrict__ W2, const float* __restrict__ Win,
                            const float* __restrict__ Hd, const float* __restrict__ x,
                            const float* __restrict__ u) {
    const int stride = gridDim.x * blockDim.x;
    const int t0 = blockIdx.x * blockDim.x + threadIdx.x;
    if (t0 == 0) g_ticket = 0;
    for (int i = t0; i < NLAUNCH + 2; i += stride) g_maxd[i] = 0.0f;
    for (int i = t0; i < D_H * D_H; i += stride) {
        split_packW(W0, g_W0hp, g_W0lp, i);
        split_packW(W1, g_W1hp, g_W1lp, i);
        split_packW(W2, g_W2hp, g_W2lp, i);
    }
    for (int i = t0; i < D_H * D_IN; i += stride) split_plain(Win, g_Winhi, g_Winlo, i);
    for (int i = t0; i < D_OUT * D_H; i += stride) split_plain(Hd, g_Hdhi, g_Hdlo, i);
    for (int i = t0; i < BATCH * D_IN; i += stride) split_plain(x, g_xhi, g_xlo, i);
    for (int i = t0; i < BATCH * D_H; i += stride) {
        g_S[0][i] = 0.0f; g_S[1][i] = 0.0f; g_S[2][i] = 0.0f;
        g_hring[0][i] = 0.0f; g_hring[1][i] = 0.0f;
        g_hring[2][i] = 0.0f; g_hring[3][i] = 0.0f;
    }
    for (int i = t0; i < (int)(HPK_BYTES / 4); i += stride) {
        reinterpret_cast<uint32_t*>(g_dPhA)[i] = 0u;
        reinterpret_cast<uint32_t*>(g_dPlA)[i] = 0u;
    }
    for (int j = t0; j < D_IN; j += stride) {
        float acc = 0.0f;
#pragma unroll 4
        for (int i = 0; i < D_H; i++) acc = fmaf(Win[(size_t)i * D_IN + j], u[i], acc);
        g_t[j] = acc;
    }
}

// ---------------- sigma ----------------
__global__ void sigma_kernel(const float* __restrict__ W, const float* __restrict__ t,
                             float* __restrict__ s, float* __restrict__ scal) {
    __shared__ float shw[8];
    __shared__ int lastf;
    const int tid = threadIdx.x;
    const int lane = tid & 31;
    const int w = tid >> 5;
    float ss = 0.0f;
#pragma unroll
    for (int i = 0; i < 4; i++) {
        float v = t[tid + (i << 8)];
        ss = fmaf(v, v, ss);
    }
#pragma unroll
    for (int o = 16; o > 0; o >>= 1) ss += __shfl_xor_sync(0xffffffffu, ss, o);
    if (lane == 0) shw[w] = ss;
    __syncthreads();
    float tot = shw[lane & 7];
#pragma unroll
    for (int o = 4; o > 0; o >>= 1) tot += __shfl_xor_sync(0xffffffffu, tot, o);
    const float invn = 1.0f / (sqrtf(tot) + EPSV);

    const int gwarp = blockIdx.x * 8 + w;
    for (int r = gwarp; r < D_H; r += 512) {
        const float* row = W + (size_t)r * D_IN;
        float acc = 0.0f;
        for (int j = lane; j < D_IN; j += 32) acc = fmaf(row[j], t[j], acc);
#pragma unroll
        for (int o = 16; o > 0; o >>= 1) acc += __shfl_xor_sync(0xffffffffu, acc, o);
        if (lane == 0) s[r] = acc * invn;
    }
    __threadfence();
    if (tid == 0) lastf = (atomicAdd(&g_ticket, 1) == (int)gridDim.x - 1);
    __syncthreads();
    if (lastf) {
        __threadfence();
        float q = 0.0f;
        for (int i = tid; i < D_H; i += 256) { float v = s[i]; q = fmaf(v, v, q); }
#pragma unroll
        for (int o = 16; o > 0; o >>= 1) q += __shfl_xor_sync(0xffffffffu, q, o);
        if (lane == 0) shw[w] = q;
        __syncthreads();
        if (tid == 0) {
            float Q = 0.0f;
#pragma unroll
            for (int i = 0; i < 8; i++) Q += shw[i];
            scal[1] = (sqrtf(Q) + EPSV) / Q;
        }
    }
}

// ================= bf16 3-pass aux GEMM (x_proj MODE 0, head MODE 2) =================
template <int AP>
__device__ __forceinline__ void prefetch_chunk(uint32_t sb_u, char* sb_p, int k0,
        const void* Ahi, const void* Alo,
        const __nv_bfloat16* __restrict__ Bhi, const __nv_bfloat16* __restrict__ Blo,
        int K, int NB, int m0, int n0) {
    const int t = threadIdx.x;
#pragma unroll
    for (int r = 0; r < 4; r++) {
        const int idx = t + (r << 7);
        const int row = idx >> 3;
        const int c   = idx & 7;
        const uint32_t soff = (uint32_t)row * ROW_B + (c << 4);
        const void *pa, *pl;
        if (AP == 0) {
            const size_t ga = (size_t)(m0 + row) * K + k0 + (c << 3);
            pa = (const __nv_bfloat16*)Ahi + ga;
            pl = (const __nv_bfloat16*)Alo + ga;
        } else {
            const size_t gb = ((size_t)((m0 >> 6) * NKCH + (k0 >> 7))) * ATILE +
                              (size_t)row * SROW + ((k0 & 127) << 1) + (c << 4);
            pa = (const char*)Ahi + gb;
            pl = (const char*)Alo + gb;
        }
        CP16(sb_u + TILE_A_HI + soff, pa);
        CP16(sb_u + TILE_A_LO + soff, pl);
        const int gn = n0 + row;
        if (gn < NB) {
            const size_t gb2 = (size_t)gn * K + k0 + (c << 3);
            CP16(sb_u + TILE_B_HI + soff, Bhi + gb2);
            CP16(sb_u + TILE_B_LO + soff, Blo + gb2);
        } else {
            const uint4 z = make_uint4(0, 0, 0, 0);
            *reinterpret_cast<uint4*>(sb_p + TILE_B_HI + soff) = z;
            *reinterpret_cast<uint4*>(sb_p + TILE_B_LO + soff) = z;
        }
    }
}

template <int MODE, int AP>
__global__ void __launch_bounds__(128)
gemm_mma(const void* Ahi, const void* Alo,
         const __nv_bfloat16* __restrict__ Bhi, const __nv_bfloat16* __restrict__ Blo,
         const float* __restrict__ bias, float* __restrict__ outF,
         const float* __restrict__ scale_ptr, int K, int NB, int ldOut,
         const float* __restrict__ lb0, const float* __restrict__ lb1,
         const float* __restrict__ lb2, float* __restrict__ xpb) {
    extern __shared__ char smem[];
    const uint32_t sbase = smem_u32(smem);
    const int tid  = threadIdx.x;
    const int lane = tid & 31;
    const int wid  = tid >> 5;
    const int m0 = blockIdx.y * 64;
    const int n0 = blockIdx.x * 64;
    const int wm = (wid >> 1) << 5;
    const int wn = (wid & 1) << 5;
    const int NC = K >> 6;

    const int arow  = (lane & 7) | (((lane >> 3) & 1) << 3);
    const int akoff = ((lane >> 4) & 1) << 3;
    const int brow  = (lane & 7) | (((lane >> 4) & 1) << 3);
    const int bkoff = ((lane >> 3) & 1) << 3;

    float acc[2][4][4] = {};

    prefetch_chunk<AP>(sbase, smem, 0, Ahi, Alo, Bhi, Blo, K, NB, m0, n0);
    CP_COMMIT();

    for (int c = 0; c < NC; c++) {
        if (c + 1 < NC) {
            const int ns = (c + 1) & 1;
            prefetch_chunk<AP>(sbase + ns * STAGE_BYTES, smem + ns * STAGE_BYTES,
                               (c + 1) << 6, Ahi, Alo, Bhi, Blo, K, NB, m0, n0);
            CP_COMMIT();
            CP_WAIT(1);
        } else {
            CP_WAIT(0);
        }
        __syncthreads();

        const uint32_t st = sbase + (c & 1) * STAGE_BYTES;
#pragma unroll
        for (int kk = 0; kk < 4; kk++) {
            const int k0 = kk << 4;
            uint32_t ah[2][4], al[2][4], bh[2][4], bl[2][4];
#pragma unroll
            for (int a = 0; a < 2; a++) {
                const uint32_t off = (uint32_t)(wm + (a << 4) + arow) * ROW_B +
                                     ((k0 + akoff) << 1);
                ldsm4(ah[a], st + TILE_A_HI + off);
                ldsm4(al[a], st + TILE_A_LO + off);
            }
#pragma unroll
            for (int b = 0; b < 2; b++) {
                const uint32_t off = (uint32_t)(wn + (b << 4) + brow) * ROW_B +
                                     ((k0 + bkoff) << 1);
                ldsm4(bh[b], st + TILE_B_HI + off);
                ldsm4(bl[b], st + TILE_B_LO + off);
            }
#pragma unroll
            for (int a = 0; a < 2; a++)
#pragma unroll
                for (int j = 0; j < 4; j++)
                    mma_bf16(acc[a][j], ah[a], &bh[j >> 1][(j & 1) << 1]);
#pragma unroll
            for (int a = 0; a < 2; a++)
#pragma unroll
                for (int j = 0; j < 4; j++)
                    mma_bf16(acc[a][j], ah[a], &bl[j >> 1][(j & 1) << 1]);
#pragma unroll
            for (int a = 0; a < 2; a++)
#pragma unroll
                for (int j = 0; j < 4; j++)
                    mma_bf16(acc[a][j], al[a], &bh[j >> 1][(j & 1) << 1]);
        }
        __syncthreads();
    }

    const float scale = (MODE == 0) ? *scale_ptr : 1.0f;
    const int g  = lane >> 2;
    const int i2 = (lane & 3) << 1;
#pragma unroll
    for (int a = 0; a < 2; a++)
#pragma unroll
        for (int j = 0; j < 4; j++)
#pragma unroll
            for (int e = 0; e < 4; e++) {
                const int m = m0 + wm + (a << 4) + g + ((e >> 1) << 3);
                const int n = n0 + wn + (j << 3) + i2 + (e & 1);
                const float r = acc[a][j][e];
                if (MODE == 0) {
                    const float v = fmaf(r, scale, bias[n]);
                    const size_t idx = (size_t)m * D_H + n;
                    xpb[idx] = v + lb0[n];
                    xpb[(size_t)BATCH * D_H + idx] = v + lb1[n];
                    xpb[(size_t)2 * BATCH * D_H + idx] = v + lb2[n];
                } else {
                    if (n < NB) outF[(size_t)m * ldOut + n] = r + bias[n];
                }
            }
}

// ====== step GEMM: delta-form, adaptive pass count AND pipeline depth ======
__global__ void __launch_bounds__(128)
gemm_step(const char* __restrict__ dAH, const char* __restrict__ dAL,
          const char* __restrict__ WH, const char* __restrict__ WL,
          const float* __restrict__ xpb, float* __restrict__ Sacc,
          const float* __restrict__ hold, const float* __restrict__ h3,
          float* __restrict__ outF,
          char* __restrict__ dNxtH, char* __restrict__ dNxtL,
          char* __restrict__ hPh, char* __restrict__ hPl,
          float* __restrict__ maxd, int lidx) {
    extern __shared__ char smem[];
    const uint32_t sbase = smem_u32(smem);
    const uint32_t data0 = sbase + S_DATA;
    const int tid  = threadIdx.x;
    const int lane = tid & 31;
    const int wid  = tid >> 5;
    const int wk   = wid & 1;
    const int wq   = wid >> 1;
    const int nt = blockIdx.x;
    const int mt = blockIdx.y;
    const int m0 = mt << 6;
    const int n0 = nt << 5;
    const int wm = wq << 5;
    const int NC = NKCH;

    // adaptive pass count from previous launch's max |delta|
    const float md = __ldg(&maxd[lidx]);
    const int p3 = (md >= 2e-2f);
    const int p2 = (md >= 2e-3f);
    const uint32_t tx  = 17408u + 8704u + (p2 ? 8704u : 0u) + (p3 ? 17408u : 0u);
    const uint32_t ssz = tx;                      // stage size = bytes actually loaded
    const int nst = p3 ? 2 : (p2 ? 3 : 4);        // 2/3/4 stages fit in the pool
    const uint64_t polW = mkpolicy_last();

    const int arow  = (lane & 7) | (((lane >> 3) & 1) << 3);
    const int akoff = ((lane >> 4) & 1) << 3;
    const int brow  = (lane & 7) | (((lane >> 4) & 1) << 3);
    const int bkoff = ((lane >> 3) & 1) << 3;
    const int kbase = wk << 2;

    float accm[2][4][4] = {};
    float acc1[2][4][4] = {};
    float acc2[2][4][4] = {};

    if (tid == 0) {
#pragma unroll
        for (int i = 0; i < 4; i++) MBAR_INIT(sbase + (i << 4), 1);
    }
    __syncthreads();
    // prologue: issue chunks 0 .. nst-2
    if (tid == 0) {
        for (int i = 0; i < nst - 1; i++) {
            const uint32_t mb = sbase + (i << 4);
            const uint32_t dst = data0 + i * ssz;
            MBAR_EXPECT(mb, tx);
            const size_t ab = ((size_t)(mt * NKCH + i)) * ATILE;
            const size_t bb = ((size_t)(nt * NKCH + i)) * BTILE;
            BULKA(dst + S2_AH, dAH + ab, mb);
            BULKB_W(dst + S2_BH, WH + bb, mb, polW);
            if (p2) BULKB_W(dst + S2_BL, WL + bb, mb, polW);
            if (p3) BULKA(dst + S2_AL, dAL + ab, mb);
        }
    }

    uint32_t phase = 0;
    int s = 0;
    for (int c = 0; c < NC; c++) {
        const int cnext = c + nst - 1;
        if (cnext < NC) {
            __syncthreads();   // all warps finished reading the stage being reused
            if (tid == 0) {
                const int si = (s == 0) ? (nst - 1) : (s - 1);
                const uint32_t mb = sbase + (si << 4);
                const uint32_t dst = data0 + si * ssz;
                MBAR_EXPECT(mb, tx);
                const size_t ab = ((size_t)(mt * NKCH + cnext)) * ATILE;
                const size_t bb = ((size_t)(nt * NKCH + cnext)) * BTILE;
                BULKA(dst + S2_AH, dAH + ab, mb);
                BULKB_W(dst + S2_BH, WH + bb, mb, polW);
                if (p2) BULKB_W(dst + S2_BL, WL + bb, mb, polW);
                if (p3) BULKA(dst + S2_AL, dAL + ab, mb);
            }
        }
        MBAR_WAIT(sbase + (s << 4), (phase >> s) & 1);
        phase ^= (1u << s);

        const uint32_t st = data0 + s * ssz;
#pragma unroll
        for (int kki = 0; kki < 4; kki++) {
            const int k0 = (kbase + kki) << 4;
            uint32_t ah[2][4], al[2][4], bh[2][4], bl[2][4];
#pragma unroll
            for (int a = 0; a < 2; a++) {
                const uint32_t off = (uint32_t)(wm + (a << 4) + arow) * SROW +
                                     ((k0 + akoff) << 1);
                ldsm4(ah[a], st + S2_AH + off);
            }
            if (p3)
#pragma unroll
                for (int a = 0; a < 2; a++) {
                    const uint32_t off = (uint32_t)(wm + (a << 4) + arow) * SROW +
                                         ((k0 + akoff) << 1);
                    ldsm4(al[a], st + S2_AL + off);
                }
#pragma unroll
            for (int b = 0; b < 2; b++) {
                const uint32_t off = (uint32_t)((b << 4) + brow) * SROW +
                                     ((k0 + bkoff) << 1);
                ldsm4(bh[b], st + S2_BH + off);
            }
            if (p2)
#pragma unroll
                for (int b = 0; b < 2; b++) {
                    const uint32_t off = (uint32_t)((b << 4) + brow) * SROW +
                                         ((k0 + bkoff) << 1);
                    ldsm4(bl[b], st + S2_BL + off);
                }
#pragma unroll
            for (int a = 0; a < 2; a++)
#pragma unroll
                for (int j = 0; j < 4; j++)
                    mma_bf16(accm[a][j], ah[a], &bh[j >> 1][(j & 1) << 1]);
            if (p2)
#pragma unroll
                for (int a = 0; a < 2; a++)
#pragma unroll
                    for (int j = 0; j < 4; j++)
                        mma_bf16(acc1[a][j], ah[a], &bl[j >> 1][(j & 1) << 1]);
            if (p3)
#pragma unroll
                for (int a = 0; a < 2; a++)
#pragma unroll
                    for (int j = 0; j < 4; j++)
                        mma_bf16(acc2[a][j], al[a], &bh[j >> 1][(j & 1) << 1]);
        }
        s = (s + 1 >= nst) ? 0 : (s + 1);
    }

    float rsum[2][4][4];
#pragma unroll
    for (int a = 0; a < 2; a++)
#pragma unroll
        for (int j = 0; j < 4; j++)
#pragma unroll
            for (int e = 0; e < 4; e++)
                rsum[a][j][e] = accm[a][j][e] + acc1[a][j][e] + acc2[a][j][e];

    __syncthreads();
    float* red = reinterpret_cast<float*>(smem + S_DATA);
    if (wk == 1) {
        float* dst = red + (wq << 10);
#pragma unroll
        for (int a = 0; a < 2; a++)
#pragma unroll
            for (int j = 0; j < 4; j++)
#pragma unroll
                for (int e = 0; e < 4; e++)
                    dst[((a << 4) | (j << 2) | e) << 5 | lane] = rsum[a][j][e];
    }
    __syncthreads();
    if (wk == 0) {
        const float* src = red + (wq << 10);
#pragma unroll
        for (int a = 0; a < 2; a++)
#pragma unroll
            for (int j = 0; j < 4; j++)
#pragma unroll
                for (int e = 0; e < 4; e++)
                    rsum[a][j][e] += src[((a << 4) | (j << 2) | e) << 5 | lane];

        float dmax = 0.0f;
        const int g  = lane >> 2;
        const int i2 = (lane & 3) << 1;
#pragma unroll
        for (int a = 0; a < 2; a++)
#pragma unroll
            for (int j = 0; j < 4; j++)
#pragma unroll
                for (int eh = 0; eh < 2; eh++) {
                    const int m = m0 + wm + (a << 4) + g + (eh << 3);
                    const int n = n0 + (j << 3) + i2;
                    const size_t idx = (size_t)m * D_H + n;
                    const float r0 = rsum[a][j][eh * 2 + 0];
                    const float r1 = rsum[a][j][eh * 2 + 1];
                    const float2 So = *reinterpret_cast<const float2*>(Sacc + idx);
                    const float Sn0 = So.x + r0, Sn1 = So.y + r1;
                    *reinterpret_cast<float2*>(Sacc + idx) = make_float2(Sn0, Sn1);
                    const float2 xb = *reinterpret_cast<const float2*>(xpb + idx);
                    const float2 ho = *reinterpret_cast<const float2*>(hold + idx);
                    const float hn0 = 0.5f * ho.x + 0.5f * tanhf(xb.x + Sn0);
                    const float hn1 = 0.5f * ho.y + 0.5f * tanhf(xb.y + Sn1);
                    *reinterpret_cast<float2*>(outF + idx) = make_float2(hn0, hn1);
                    const float2 h3v = *reinterpret_cast<const float2*>(h3 + idx);
                    const float d0 = hn0 - h3v.x, d1 = hn1 - h3v.y;
                    dmax = fmaxf(dmax, fmaxf(fabsf(d0), fabsf(d1)));
                    const __nv_bfloat16 dh0 = __float2bfloat16(d0);
                    const __nv_bfloat16 dh1 = __float2bfloat16(d1);
                    __nv_bfloat162 hv, lv;
                    hv.x = dh0; hv.y = dh1;
                    lv.x = __float2bfloat16(d0 - __bfloat162float(dh0));
                    lv.y = __float2bfloat16(d1 - __bfloat162float(dh1));
                    const size_t pidx = pkoff(m, n);
                    *reinterpret_cast<__nv_bfloat162*>(dNxtH + pidx) = hv;
                    *reinterpret_cast<__nv_bfloat162*>(dNxtL + pidx) = lv;
                    if (lidx == NLAUNCH - 1) {
                        const __nv_bfloat16 b0 = __float2bfloat16(hn0);
                        const __nv_bfloat16 b1 = __float2bfloat16(hn1);
                        __nv_bfloat162 hh, hl;
                        hh.x = b0; hh.y = b1;
                        hl.x = __float2bfloat16(hn0 - __bfloat162float(b0));
                        hl.y = __float2bfloat16(hn1 - __bfloat162float(b1));
                        *reinterpret_cast<__nv_bfloat162*>(hPh + pidx) = hh;
                        *reinterpret_cast<__nv_bfloat162*>(hPl + pidx) = hl;
                    }
                }
#pragma unroll
        for (int o = 16; o > 0; o >>= 1)
            dmax = fmaxf(dmax, __shfl_xor_sync(0xffffffffu, dmax, o));
        if (lane == 0)
            atomicMax(reinterpret_cast<int*>(&maxd[lidx + 1]), __float_as_int(dmax));
    }
}

// ---------------- host ----------------
extern "C" void kernel_launch(void* const* d_in, const int* in_sizes, int n_in,
                              void* d_out, int out_size) {
    const float* x     = (const float*)d_in[0];
    const float* Winw  = (const float*)d_in[1];
    const float* Winb  = (const float*)d_in[2];
    const float* u     = (const float*)d_in[3];
    const float* W0    = (const float*)d_in[4];
    const float* b0    = (const float*)d_in[5];
    const float* W1    = (const float*)d_in[6];
    const float* b1    = (const float*)d_in[7];
    const float* W2    = (const float*)d_in[8];
    const float* b2    = (const float*)d_in[9];
    const float* headw = (const float*)d_in[10];
    const float* headb = (const float*)d_in[11];
    float* out = (float*)d_out;

    float *t, *s, *scal, *xpb, *Sacc, *hr, *maxd;
    cudaGetSymbolAddress((void**)&t, g_t);
    cudaGetSymbolAddress((void**)&s, g_s);
    cudaGetSymbolAddress((void**)&scal, g_scal);
    cudaGetSymbolAddress((void**)&xpb, g_xpb);
    cudaGetSymbolAddress((void**)&Sacc, g_S);
    cudaGetSymbolAddress((void**)&hr, g_hring);
    cudaGetSymbolAddress((void**)&maxd, g_maxd);
    char *W0hp, *W0lp, *W1hp, *W1lp, *W2hp, *W2lp;
    char *dPhA, *dPlA, *dPhB, *dPlB, *hPh, *hPl;
    cudaGetSymbolAddress((void**)&W0hp, g_W0hp); cudaGetSymbolAddress((void**)&W0lp, g_W0lp);
    cudaGetSymbolAddress((void**)&W1hp, g_W1hp); cudaGetSymbolAddress((void**)&W1lp, g_W1lp);
    cudaGetSymbolAddress((void**)&W2hp, g_W2hp); cudaGetSymbolAddress((void**)&W2lp, g_W2lp);
    cudaGetSymbolAddress((void**)&dPhA, g_dPhA); cudaGetSymbolAddress((void**)&dPlA, g_dPlA);
    cudaGetSymbolAddress((void**)&dPhB, g_dPhB); cudaGetSymbolAddress((void**)&dPlB, g_dPlB);
    cudaGetSymbolAddress((void**)&hPh, g_hPh);   cudaGetSymbolAddress((void**)&hPl, g_hPl);
    __nv_bfloat16 *Winh, *Winl, *Hdh, *Hdl, *xh, *xl;
    cudaGetSymbolAddress((void**)&Winh, g_Winhi); cudaGetSymbolAddress((void**)&Winl, g_Winlo);
    cudaGetSymbolAddress((void**)&Hdh, g_Hdhi);   cudaGetSymbolAddress((void**)&Hdl, g_Hdlo);
    cudaGetSymbolAddress((void**)&xh, g_xhi);     cudaGetSymbolAddress((void**)&xl, g_xlo);

    cudaFuncSetAttribute(gemm_mma<0, 0>, cudaFuncAttributeMaxDynamicSharedMemorySize, SMEM_BYTES);
    cudaFuncSetAttribute(gemm_mma<2, 1>, cudaFuncAttributeMaxDynamicSharedMemorySize, SMEM_BYTES);
    cudaFuncSetAttribute(gemm_step, cudaFuncAttributeMaxDynamicSharedMemorySize, S_SMEM);

    prep_kernel<<<592, 256>>>(W0, W1, W2, Winw, headw, x, u);
    sigma_kernel<<<64, 256>>>(Winw, t, s, scal);
    {
        dim3 grid(D_H / 64, BATCH / 64);
        gemm_mma<0, 0><<<grid, 128, SMEM_BYTES>>>(xh, xl, Winh, Winl, Winb,
                                                  nullptr, scal + 1, D_IN, D_H, D_H,
                                                  b0, b1, b2, xpb);
    }

    const char* Whp[3] = {W0hp, W1hp, W2hp};
    const char* Wlp[3] = {W0lp, W1lp, W2lp};
    char* dH[2] = {dPhA, dPhB};
    char* dL[2] = {dPlA, dPlB};
    const size_t HN = (size_t)BATCH * D_H;
    dim3 gstep(D_H / 32, BATCH / 64);
    for (int sidx = 0; sidx < NLAUNCH; sidx++) {
        const int l = sidx % 3;
        gemm_step<<<gstep, 128, S_SMEM>>>(
            dH[sidx & 1], dL[sidx & 1], Whp[l], Wlp[l],
            xpb + (size_t)l * HN, Sacc + (size_t)l * HN,
            hr + (size_t)((sidx + 3) & 3) * HN,     // hold = out(s-1)
            hr + (size_t)((sidx + 1) & 3) * HN,     // h3   = out(s-3)
            hr + (size_t)(sidx & 3) * HN,           // outF = out(s)
            dH[(sidx + 1) & 1], dL[(sidx + 1) & 1],
            hPh, hPl, maxd, sidx);
    }
    {
        dim3 grid((D_OUT + 63) / 64, BATCH / 64);
        gemm_mma<2, 1><<<grid, 128, SMEM_BYTES>>>(hPh, hPl, Hdh, Hdl, headb,
                                                  out, nullptr, D_H, D_OUT, D_OUT,
                                                  nullptr, nullptr, nullptr, nullptr);
    }
}